// round 1
// baseline (speedup 1.0000x reference)
#include <cuda_runtime.h>
#include <math.h>

#define N_NODES 50000
#define N_EDGES 800000
#define H 256
#define F_IN 1280
#define NLAYERS 4

// ---------------- scratch (device globals; no allocation) ----------------
__device__ float g_X0[N_NODES * H];
__device__ float g_X1[N_NODES * H];
__device__ float g_M [N_NODES * H];   // mask (sigmoid)
__device__ float g_T [N_NODES * H];   // xm / xg scatter-input buffer
__device__ float g_S [N_NODES * H];   // aggregation output
__device__ float g_Hb[N_NODES * H];   // h buffer
__device__ int   g_deg [N_NODES];
__device__ int   g_ptr [N_NODES];
__device__ int   g_fill[N_NODES];
__device__ int   g_csr [N_EDGES];
__device__ float g_degf[N_NODES];
__device__ int   g_bsum[64];

// ---------------- CSR build ----------------
__global__ void k_zero_deg() {
    int i = blockIdx.x * blockDim.x + threadIdx.x;
    if (i < N_NODES) g_deg[i] = 0;
}

__global__ void k_hist(const int* __restrict__ dst) {
    int e = blockIdx.x * blockDim.x + threadIdx.x;
    if (e < N_EDGES) atomicAdd(&g_deg[dst[e]], 1);
}

__global__ void k_scan_block() {
    __shared__ int sh[1024];
    int i = blockIdx.x * 1024 + threadIdx.x;
    int v = (i < N_NODES) ? g_deg[i] : 0;
    sh[threadIdx.x] = v;
    __syncthreads();
    for (int off = 1; off < 1024; off <<= 1) {
        int t = (threadIdx.x >= off) ? sh[threadIdx.x - off] : 0;
        __syncthreads();
        sh[threadIdx.x] += t;
        __syncthreads();
    }
    if (i < N_NODES) g_ptr[i] = sh[threadIdx.x] - v;   // exclusive
    if (threadIdx.x == 1023) g_bsum[blockIdx.x] = sh[1023];
}

__global__ void k_scan_sums(int nb) {
    if (threadIdx.x == 0 && blockIdx.x == 0) {
        int run = 0;
        for (int b = 0; b < nb; b++) { int t = g_bsum[b]; g_bsum[b] = run; run += t; }
    }
}

__global__ void k_finalize() {
    int i = blockIdx.x * 1024 + threadIdx.x;
    if (i < N_NODES) {
        int p = g_ptr[i] + g_bsum[blockIdx.x];
        g_ptr[i]  = p;
        g_fill[i] = p;
        g_degf[i] = (float)g_deg[i];
    }
}

__global__ void k_fill_csr(const int* __restrict__ src, const int* __restrict__ dst) {
    int e = blockIdx.x * blockDim.x + threadIdx.x;
    if (e < N_EDGES) {
        int p = atomicAdd(&g_fill[dst[e]], 1);
        g_csr[p] = src[e];
    }
}

// ---------------- CSR gather-aggregate: S[n] = sum_{u in nbr(n)} X[u] ----------------
// 64 threads per node, one float4 per thread (H=256 = 64 float4)
__global__ void k_aggregate(const float4* __restrict__ Xin, float4* __restrict__ Sout) {
    int node = blockIdx.x * 4 + (threadIdx.x >> 6);
    int lane = threadIdx.x & 63;
    if (node >= N_NODES) return;
    int s = g_ptr[node];
    int d = g_deg[node];
    float4 acc = make_float4(0.f, 0.f, 0.f, 0.f);
    for (int e = s; e < s + d; e++) {
        int u = __ldg(&g_csr[e]);
        float4 v = __ldg(&Xin[(size_t)u * 64 + lane]);
        acc.x += v.x; acc.y += v.y; acc.z += v.z; acc.w += v.w;
    }
    Sout[(size_t)node * 64 + lane] = acc;
}

// ---------------- fused fp32 GEMM: C = [A0|A1] @ [W0;W1] + epilogue ----------------
// BM=128, BN=128, BK=16, 256 threads, 8x8 per thread (split as 2 x float4 column chunks)
// MODE 0 (lin0): C = acc + b            ; C2 = C (xm for layer 0)
// MODE 1 (h)   : C = relu(acc + b1 + degf[m]*b2)
// MODE 2 (mask): mk = sigmoid(acc + b3) ; C = mk ; C2 = mk * Xin  (= xg)
// MODE 3 (x')  : v = relu(acc + bn)     ; C = v  ; C2 = v * Mask  (= xm next) ; Dout = v
#define BM 128
#define BN 128
#define BK 16

template<int MODE>
__global__ void __launch_bounds__(256, 2) k_gemm(
    const float* __restrict__ A0, const float* __restrict__ W0, int K0,
    const float* __restrict__ A1, const float* __restrict__ W1, int K1,
    const float* __restrict__ bias,
    const float* __restrict__ bias2,
    float* __restrict__ C,
    float* __restrict__ C2,
    const float* __restrict__ Xin,
    const float* __restrict__ Mask,
    float* __restrict__ Dout)
{
    __shared__ float As[BK][BM + 4];
    __shared__ float Ws[BK][BN];

    const int tid = threadIdx.x;
    const int m0  = blockIdx.x * BM;
    const int n0  = blockIdx.y * BN;
    const int ty  = tid >> 4;   // 0..15 -> row group of 8
    const int tx  = tid & 15;   // 0..15 -> col group (2 x 4)

    float acc[8][8];
#pragma unroll
    for (int i = 0; i < 8; i++)
#pragma unroll
        for (int j = 0; j < 8; j++) acc[i][j] = 0.f;

    const int Ktot = K0 + K1;
    for (int kt = 0; kt < Ktot; kt += BK) {
        const float* A; const float* W; int lda; int kl;
        if (kt < K0) { A = A0; W = W0; lda = K0; kl = kt; }
        else         { A = A1; W = W1; lda = K1; kl = kt - K0; }

        // A tile: 128 rows x 16 cols = 512 float4, 2 per thread; stored transposed
#pragma unroll
        for (int l = 0; l < 2; l++) {
            int f = tid + l * 256;
            int r = f >> 2, q = f & 3;
            float4 v = make_float4(0.f, 0.f, 0.f, 0.f);
            if (m0 + r < N_NODES)
                v = *(const float4*)(A + (size_t)(m0 + r) * lda + kl + q * 4);
            As[q * 4 + 0][r] = v.x;
            As[q * 4 + 1][r] = v.y;
            As[q * 4 + 2][r] = v.z;
            As[q * 4 + 3][r] = v.w;
        }
        // W tile: 16 rows x 128 cols = 512 float4, 2 per thread
#pragma unroll
        for (int l = 0; l < 2; l++) {
            int f = tid + l * 256;
            int kr = f >> 5, c = f & 31;
            float4 v = *(const float4*)(W + (size_t)(kl + kr) * H + n0 + c * 4);
            *(float4*)&Ws[kr][c * 4] = v;
        }
        __syncthreads();

#pragma unroll
        for (int kk = 0; kk < BK; kk++) {
            float a[8], b[8];
            float4 a0 = *(const float4*)&As[kk][ty * 8];
            float4 a1 = *(const float4*)&As[kk][ty * 8 + 4];
            a[0]=a0.x; a[1]=a0.y; a[2]=a0.z; a[3]=a0.w;
            a[4]=a1.x; a[5]=a1.y; a[6]=a1.z; a[7]=a1.w;
            float4 b0 = *(const float4*)&Ws[kk][tx * 4];
            float4 b1v = *(const float4*)&Ws[kk][64 + tx * 4];
            b[0]=b0.x; b[1]=b0.y; b[2]=b0.z; b[3]=b0.w;
            b[4]=b1v.x; b[5]=b1v.y; b[6]=b1v.z; b[7]=b1v.w;
#pragma unroll
            for (int i = 0; i < 8; i++)
#pragma unroll
                for (int j = 0; j < 8; j++)
                    acc[i][j] += a[i] * b[j];
        }
        __syncthreads();
    }

    // epilogue: row m = m0+ty*8+i ; cols: n0+tx*4+{0..3} and n0+64+tx*4+{0..3}
#pragma unroll
    for (int i = 0; i < 8; i++) {
        int m = m0 + ty * 8 + i;
        if (m >= N_NODES) continue;
        float dscale = (MODE == 1) ? g_degf[m] : 0.f;
#pragma unroll
        for (int hf = 0; hf < 2; hf++) {
            int cb = n0 + hf * 64 + tx * 4;   // global col of first of 4
            float4 bb = *(const float4*)&bias[cb];
            float r[4];
#pragma unroll
            for (int j = 0; j < 4; j++) r[j] = acc[i][hf * 4 + j];
            if (MODE == 1) {
                float4 b2v = *(const float4*)&bias2[cb];
                r[0] = fmaxf(r[0] + bb.x + dscale * b2v.x, 0.f);
                r[1] = fmaxf(r[1] + bb.y + dscale * b2v.y, 0.f);
                r[2] = fmaxf(r[2] + bb.z + dscale * b2v.z, 0.f);
                r[3] = fmaxf(r[3] + bb.w + dscale * b2v.w, 0.f);
            } else {
                r[0] += bb.x; r[1] += bb.y; r[2] += bb.z; r[3] += bb.w;
            }
            size_t off = (size_t)m * H + cb;
            if (MODE == 0) {
                float4 v = make_float4(r[0], r[1], r[2], r[3]);
                *(float4*)&C [off] = v;
                *(float4*)&C2[off] = v;
            }
            if (MODE == 1) {
                *(float4*)&C[off] = make_float4(r[0], r[1], r[2], r[3]);
            }
            if (MODE == 2) {
#pragma unroll
                for (int j = 0; j < 4; j++) r[j] = 1.f / (1.f + expf(-r[j]));
                float4 xv = *(const float4*)&Xin[off];
                *(float4*)&C [off] = make_float4(r[0], r[1], r[2], r[3]);
                *(float4*)&C2[off] = make_float4(r[0]*xv.x, r[1]*xv.y, r[2]*xv.z, r[3]*xv.w);
            }
            if (MODE == 3) {
#pragma unroll
                for (int j = 0; j < 4; j++) r[j] = fmaxf(r[j], 0.f);
                float4 mv = *(const float4*)&Mask[off];
                *(float4*)&C [off] = make_float4(r[0], r[1], r[2], r[3]);
                *(float4*)&C2[off] = make_float4(r[0]*mv.x, r[1]*mv.y, r[2]*mv.z, r[3]*mv.w);
                *(float4*)&Dout[(size_t)m * (NLAYERS * H) + cb] = make_float4(r[0], r[1], r[2], r[3]);
            }
        }
    }
}

__global__ void k_tail(float* p, int n) {
    int i = blockIdx.x * blockDim.x + threadIdx.x;
    if (i < n) p[i] = 1.0f;
}

// ---------------- launch ----------------
extern "C" void kernel_launch(void* const* d_in, const int* in_sizes, int n_in,
                              void* d_out, int out_size)
{
    (void)in_sizes; (void)n_in;
    const int*   edge   = (const int*)  d_in[1];
    const float* esm    = (const float*)d_in[2];
    const float* lin0_W = (const float*)d_in[4];
    const float* lin0_b = (const float*)d_in[5];
    const float* wc_W1  = (const float*)d_in[6];
    const float* wc_b1  = (const float*)d_in[7];
    const float* wc_W2  = (const float*)d_in[8];
    const float* wc_b2  = (const float*)d_in[9];
    const float* wc_W3  = (const float*)d_in[10];
    const float* wc_b3  = (const float*)d_in[11];
    const float* sc_Wn  = (const float*)d_in[12];
    const float* sc_bn  = (const float*)d_in[13];
    const float* sc_Wr  = (const float*)d_in[14];
    float* out = (float*)d_out;

    const int* src = edge;
    const int* dst = edge + N_EDGES;

    float *pX0, *pX1, *pM, *pT, *pS, *pHb;
    cudaGetSymbolAddress((void**)&pX0, g_X0);
    cudaGetSymbolAddress((void**)&pX1, g_X1);
    cudaGetSymbolAddress((void**)&pM,  g_M);
    cudaGetSymbolAddress((void**)&pT,  g_T);
    cudaGetSymbolAddress((void**)&pS,  g_S);
    cudaGetSymbolAddress((void**)&pHb, g_Hb);

    // CSR build (per launch; deterministic up to fp-benign neighbor order)
    k_zero_deg<<<(N_NODES + 255) / 256, 256>>>();
    k_hist    <<<(N_EDGES + 255) / 256, 256>>>(dst);
    int nblk = (N_NODES + 1023) / 1024;           // 49
    k_scan_block<<<nblk, 1024>>>();
    k_scan_sums <<<1, 32>>>(nblk);
    k_finalize  <<<nblk, 1024>>>();
    k_fill_csr  <<<(N_EDGES + 255) / 256, 256>>>(src, dst);

    dim3 ggrid((N_NODES + BM - 1) / BM, H / BN);  // 391 x 2
    dim3 agrid((N_NODES + 3) / 4);                // 12500, 4 nodes/block

    // x = esm @ W0 + b0 ; xm(layer0) = x
    k_gemm<0><<<ggrid, 256>>>(esm, lin0_W, F_IN, nullptr, nullptr, 0,
                              lin0_b, nullptr, pX0, pT, nullptr, nullptr, nullptr);

    float* xc = pX0;
    float* xn = pX1;
    for (int i = 0; i < NLAYERS; i++) {
        const float* W1 = wc_W1 + (size_t)i * H * H;
        const float* W2 = wc_W2 + (size_t)i * H * H;
        const float* W3 = wc_W3 + (size_t)i * H * H;
        const float* Wn = sc_Wn + (size_t)i * H * H;
        const float* Wr = sc_Wr + (size_t)i * H * H;
        const float* b1 = wc_b1 + (size_t)i * H;
        const float* b2 = wc_b2 + (size_t)i * H;
        const float* b3 = wc_b3 + (size_t)i * H;
        const float* bn = sc_bn + (size_t)i * H;

        // S = A . xm
        k_aggregate<<<agrid, 256>>>((const float4*)pT, (float4*)pS);
        // h = relu(S@W2 + deg*b2 + xm@W1 + b1)
        k_gemm<1><<<ggrid, 256>>>(pS, W2, H, pT, W1, H,
                                  b1, b2, pHb, nullptr, nullptr, nullptr, nullptr);
        // mask = sigmoid(h@W3 + b3) ; xg = x * mask
        k_gemm<2><<<ggrid, 256>>>(pHb, W3, H, nullptr, nullptr, 0,
                                  b3, nullptr, pM, pT, xc, nullptr, nullptr);
        // S2 = A . xg
        k_aggregate<<<agrid, 256>>>((const float4*)pT, (float4*)pS);
        // x' = relu(S2@Wn + bn + x@Wr) ; xm_next = x' * mask ; dout col-block i
        k_gemm<3><<<ggrid, 256>>>(pS, Wn, H, xc, Wr, H,
                                  bn, nullptr, xn, pT, nullptr, pM, out + (size_t)i * H);

        float* tmp = xc; xc = xn; xn = tmp;
    }

    // node_mask tail (all nodes valid -> 1.0), if the output carries it
    long long tail = (long long)out_size - (long long)N_NODES * (NLAYERS * H);
    if (tail > 0) {
        k_tail<<<(int)((tail + 255) / 256), 256>>>(out + (size_t)N_NODES * (NLAYERS * H), (int)tail);
    }
}

// round 3
// speedup vs baseline: 1.4688x; 1.4688x over previous
#include <cuda_runtime.h>
#include <cuda_bf16.h>
#include <math.h>
#include <stdint.h>

#define N_NODES 50000
#define N_EDGES 800000
#define H 256
#define F_IN 1280
#define NLAYERS 4

typedef __nv_bfloat16 bf16;

// ---------------- scratch (device globals; no allocation) ----------------
__device__ __align__(256) float g_X0[N_NODES * H];
__device__ __align__(256) float g_X1[N_NODES * H];
__device__ __align__(256) float g_T [N_NODES * H];   // xm / xg (fp32, aggregation input)
__device__ __align__(256) float g_M [N_NODES * H];   // mask
__device__ __align__(256) bf16  g_X0h[N_NODES * H], g_X0l[N_NODES * H];
__device__ __align__(256) bf16  g_X1h[N_NODES * H], g_X1l[N_NODES * H];
__device__ __align__(256) bf16  g_Th [N_NODES * H], g_Tl [N_NODES * H];
__device__ __align__(256) bf16  g_Sh [N_NODES * H], g_Sl [N_NODES * H];
__device__ __align__(256) bf16  g_Hbh[N_NODES * H], g_Hbl[N_NODES * H];
__device__ __align__(256) bf16  g_Eh [N_NODES * F_IN], g_El[N_NODES * F_IN];
__device__ __align__(256) bf16  g_W0th[H * F_IN], g_W0tl[H * F_IN];      // lin0_W transposed [n][k]
__device__ __align__(256) bf16  g_Wth[NLAYERS * 5 * H * H];              // per (layer,type), [n][k]
__device__ __align__(256) bf16  g_Wtl[NLAYERS * 5 * H * H];
__device__ int   g_deg [N_NODES];
__device__ int   g_ptr [N_NODES];
__device__ int   g_fill[N_NODES];
__device__ int   g_csr [N_EDGES];
__device__ float g_degf[N_NODES];
__device__ int   g_bsum[64];

// ---------------- helpers ----------------
__device__ __forceinline__ uint32_t smem_u32(const void* p) {
    uint32_t a;
    asm("{ .reg .u64 t; cvta.to.shared.u64 t, %1; cvt.u32.u64 %0, t; }" : "=r"(a) : "l"(p));
    return a;
}
__device__ __forceinline__ void cp16(uint32_t saddr, const void* g) {
    asm volatile("cp.async.cg.shared.global [%0], [%1], 16;" :: "r"(saddr), "l"(g));
}
__device__ __forceinline__ void cp_commit() {
    asm volatile("cp.async.commit_group;" ::: "memory");
}
template<int n>
__device__ __forceinline__ void cp_wait() {
    asm volatile("cp.async.wait_group %0;" :: "n"(n) : "memory");
}
__device__ __forceinline__ void ldm4(uint32_t a, uint32_t* r) {
    asm volatile("ldmatrix.sync.aligned.m8n8.x4.shared.b16 {%0,%1,%2,%3}, [%4];"
        : "=r"(r[0]), "=r"(r[1]), "=r"(r[2]), "=r"(r[3]) : "r"(a));
}
__device__ __forceinline__ void mma16816(float* c, const uint32_t* a, const uint32_t* b) {
    asm volatile("mma.sync.aligned.m16n8k16.row.col.f32.bf16.bf16.f32 "
        "{%0,%1,%2,%3}, {%4,%5,%6,%7}, {%8,%9}, {%0,%1,%2,%3};"
        : "+f"(c[0]), "+f"(c[1]), "+f"(c[2]), "+f"(c[3])
        : "r"(a[0]), "r"(a[1]), "r"(a[2]), "r"(a[3]), "r"(b[0]), "r"(b[1]));
}

__device__ __forceinline__ unsigned pack2(float a, float b) {
    __nv_bfloat162 t = __floats2bfloat162_rn(a, b);
    return *(unsigned*)&t;
}
__device__ __forceinline__ uint2 pack4(float a, float b, float c, float d) {
    uint2 r; r.x = pack2(a, b); r.y = pack2(c, d); return r;
}
__device__ __forceinline__ float bflo(float a) {
    return a - __bfloat162float(__float2bfloat16(a));
}

// ---------------- CSR build ----------------
__global__ void k_zero_deg() {
    int i = blockIdx.x * blockDim.x + threadIdx.x;
    if (i < N_NODES) g_deg[i] = 0;
}
__global__ void k_hist(const int* __restrict__ dst) {
    int e = blockIdx.x * blockDim.x + threadIdx.x;
    if (e < N_EDGES) atomicAdd(&g_deg[dst[e]], 1);
}
__global__ void k_scan_block() {
    __shared__ int sh[1024];
    int i = blockIdx.x * 1024 + threadIdx.x;
    int v = (i < N_NODES) ? g_deg[i] : 0;
    sh[threadIdx.x] = v;
    __syncthreads();
    for (int off = 1; off < 1024; off <<= 1) {
        int t = (threadIdx.x >= off) ? sh[threadIdx.x - off] : 0;
        __syncthreads();
        sh[threadIdx.x] += t;
        __syncthreads();
    }
    if (i < N_NODES) g_ptr[i] = sh[threadIdx.x] - v;
    if (threadIdx.x == 1023) g_bsum[blockIdx.x] = sh[1023];
}
__global__ void k_scan_sums(int nb) {
    if (threadIdx.x == 0 && blockIdx.x == 0) {
        int run = 0;
        for (int b = 0; b < nb; b++) { int t = g_bsum[b]; g_bsum[b] = run; run += t; }
    }
}
__global__ void k_finalize() {
    int i = blockIdx.x * 1024 + threadIdx.x;
    if (i < N_NODES) {
        int p = g_ptr[i] + g_bsum[blockIdx.x];
        g_ptr[i]  = p;
        g_fill[i] = p;
        g_degf[i] = (float)g_deg[i];
    }
}
__global__ void k_fill_csr(const int* __restrict__ src, const int* __restrict__ dst) {
    int e = blockIdx.x * blockDim.x + threadIdx.x;
    if (e < N_EDGES) {
        int p = atomicAdd(&g_fill[dst[e]], 1);
        g_csr[p] = src[e];
    }
}

// ---------------- splits ----------------
__global__ void k_split(const float4* __restrict__ src, uint2* __restrict__ hi,
                        uint2* __restrict__ lo, int n4) {
    int i = blockIdx.x * blockDim.x + threadIdx.x;
    if (i < n4) {
        float4 v = __ldg(&src[i]);
        hi[i] = pack4(v.x, v.y, v.z, v.w);
        lo[i] = pack4(bflo(v.x), bflo(v.y), bflo(v.z), bflo(v.w));
    }
}
__global__ void k_splitT0(const float* __restrict__ W) {
    int i = blockIdx.x * blockDim.x + threadIdx.x;
    if (i < F_IN * H) {
        int k = i >> 8, n = i & 255;
        float v = __ldg(&W[i]);
        g_W0th[n * F_IN + k] = __float2bfloat16(v);
        g_W0tl[n * F_IN + k] = __float2bfloat16(bflo(v));
    }
}
__global__ void k_splitW(const float* __restrict__ W1, const float* __restrict__ W2,
                         const float* __restrict__ W3, const float* __restrict__ Wn,
                         const float* __restrict__ Wr) {
    int i = blockIdx.x * blockDim.x + threadIdx.x;
    const int per_type = NLAYERS * H * H;
    if (i < 5 * per_type) {
        int t = i / per_type;
        int r = i - t * per_type;
        int layer = r >> 16;
        int idx = r & 65535;
        int k = idx >> 8, n = idx & 255;
        const float* src = (t == 0) ? W1 : (t == 1) ? W2 : (t == 2) ? W3 : (t == 3) ? Wn : Wr;
        float v = __ldg(&src[r]);
        size_t d = (size_t)(layer * 5 + t) * 65536 + n * 256 + k;
        g_Wth[d] = __float2bfloat16(v);
        g_Wtl[d] = __float2bfloat16(bflo(v));
    }
}

// ---------------- CSR gather-aggregate -> bf16 hi/lo ----------------
__global__ void k_aggregate(const float4* __restrict__ Xin,
                            uint2* __restrict__ Sh, uint2* __restrict__ Sl) {
    int node = blockIdx.x * 4 + (threadIdx.x >> 6);
    int lane = threadIdx.x & 63;
    if (node >= N_NODES) return;
    int s = g_ptr[node];
    int d = g_deg[node];
    float4 acc = make_float4(0.f, 0.f, 0.f, 0.f);
    for (int e = s; e < s + d; e++) {
        int u = __ldg(&g_csr[e]);
        float4 v = __ldg(&Xin[(size_t)u * 64 + lane]);
        acc.x += v.x; acc.y += v.y; acc.z += v.z; acc.w += v.w;
    }
    size_t o = (size_t)node * 64 + lane;
    Sh[o] = pack4(acc.x, acc.y, acc.z, acc.w);
    Sl[o] = pack4(bflo(acc.x), bflo(acc.y), bflo(acc.z), bflo(acc.w));
}

// ---------------- mma.sync GEMM: D[128 x 128] per CTA, 3-term bf16 split ----------------
// smem stage: Ah,Al: 128x64 bf16 pad-72 ; Bh,Bl: 128x64 bf16 pad-72
#define ROWB 144            // 72 elements * 2B
#define OFF_AH 0
#define OFF_AL 18432
#define OFF_BH 36864
#define OFF_BL 55296
#define STAGE_BYTES 73728
#define DSMEM_BYTES (2 * STAGE_BYTES + 1024)

struct Tiles {
    const bf16 *A0h, *A0l, *A1h, *A1l;
    const bf16 *B0h, *B0l, *B1h, *B1l;
    int K0, K1;
};

__device__ __forceinline__ void load_stage_async(uint32_t st, int tid, int m0, int n0,
                                                 int kt, const Tiles& t) {
    const bf16 *Ah, *Al, *Bh, *Bl; int K, kl;
    if (kt < t.K0) { Ah = t.A0h; Al = t.A0l; Bh = t.B0h; Bl = t.B0l; K = t.K0; kl = kt; }
    else           { Ah = t.A1h; Al = t.A1l; Bh = t.B1h; Bl = t.B1l; K = t.K1; kl = kt - t.K0; }
    #pragma unroll
    for (int l = 0; l < 4; l++) {
        int f = tid + l * 256;
        int r = f >> 3, q = f & 7;
        int m = m0 + r; if (m >= N_NODES) m = N_NODES - 1;
        size_t g = (size_t)m * K + kl + q * 8;
        uint32_t s = st + r * ROWB + q * 16;
        cp16(s + OFF_AH, Ah + g);
        cp16(s + OFF_AL, Al + g);
    }
    #pragma unroll
    for (int l = 0; l < 4; l++) {
        int f = tid + l * 256;
        int r = f >> 3, q = f & 7;
        size_t g = (size_t)(n0 + r) * K + kl + q * 8;
        uint32_t s = st + r * ROWB + q * 16;
        cp16(s + OFF_BH, Bh + g);
        cp16(s + OFF_BL, Bl + g);
    }
}

// MODE 0 (lin0): v = acc+b       -> OA,OAh,OAl and OB,OBh,OBl (duplicate)
// MODE 1 (h)   : v = relu(acc+b1+deg*b2) -> OAh,OAl
// MODE 2 (mask): mk=sigmoid(acc+b3) -> OA=mask; OB = mk*Xin (xg, fp32 only)
// MODE 3 (x')  : v = relu(acc+bn) -> OA,OAh,OAl; OB=v*Mask,OBh,OBl; Dout
template<int MODE>
__global__ void __launch_bounds__(256, 1) k_mma(
    const bf16* A0h, const bf16* A0l, int K0,
    const bf16* A1h, const bf16* A1l, int K1,
    const bf16* B0h, const bf16* B0l,
    const bf16* B1h, const bf16* B1l,
    const float* __restrict__ bias, const float* __restrict__ bias2,
    float* __restrict__ OA, bf16* __restrict__ OAh, bf16* __restrict__ OAl,
    float* __restrict__ OB, bf16* __restrict__ OBh, bf16* __restrict__ OBl,
    const float* __restrict__ Xin, const float* __restrict__ Mask,
    float* __restrict__ Dout)
{
    extern __shared__ char dsm_raw[];
    char* sbase = (char*)(((uintptr_t)dsm_raw + 1023) & ~(uintptr_t)1023);
    const uint32_t sb32 = smem_u32(sbase);

    const int tid = threadIdx.x;
    const int wid = tid >> 5;
    const int lane = tid & 31;
    const int wm = wid & 3;     // 4 m-groups of 32 rows
    const int wn = wid >> 2;    // 2 n-groups of 64 cols
    const int m0 = blockIdx.x * 128;
    const int n0 = blockIdx.y * 128;

    Tiles t; t.A0h = A0h; t.A0l = A0l; t.A1h = A1h; t.A1l = A1l;
    t.B0h = B0h; t.B0l = B0l; t.B1h = B1h; t.B1l = B1l; t.K0 = K0; t.K1 = K1;

    float c[2][8][4];
    #pragma unroll
    for (int i = 0; i < 2; i++)
        #pragma unroll
        for (int j = 0; j < 8; j++)
            #pragma unroll
            for (int q = 0; q < 4; q++) c[i][j][q] = 0.f;

    const int nIter = (K0 + K1) >> 6;

    load_stage_async(sb32, tid, m0, n0, 0, t);
    cp_commit();

    // fragment address bases (lane-dependent, stage-relative)
    const uint32_t aAddrBase = (wm * 32 + (lane & 15)) * ROWB + (lane >> 4) * 16;
    const uint32_t bAddrBase = (wn * 64 + (lane & 7) + ((lane >> 4) & 1) * 8) * ROWB
                             + ((lane >> 3) & 1) * 16;

    for (int it = 0; it < nIter; ++it) {
        const uint32_t stu = sb32 + (it & 1) * STAGE_BYTES;
        if (it + 1 < nIter) {
            load_stage_async(sb32 + ((it + 1) & 1) * STAGE_BYTES, tid, m0, n0, (it + 1) << 6, t);
            cp_commit();
            cp_wait<1>();
        } else {
            cp_wait<0>();
        }
        __syncthreads();

        #pragma unroll
        for (int term = 0; term < 3; term++) {
            const uint32_t aOff = stu + ((term < 2) ? OFF_AH : OFF_AL);
            const uint32_t bOff = stu + ((term == 1) ? OFF_BL : OFF_BH);
            #pragma unroll
            for (int ks = 0; ks < 4; ks++) {
                const uint32_t kb = ks * 32;   // 16 elements * 2B
                uint32_t af[2][4];
                #pragma unroll
                for (int mt = 0; mt < 2; mt++)
                    ldm4(aOff + aAddrBase + mt * (16 * ROWB) + kb, af[mt]);
                uint32_t bf[4][4];
                #pragma unroll
                for (int nt2 = 0; nt2 < 4; nt2++)
                    ldm4(bOff + bAddrBase + nt2 * (16 * ROWB) + kb, bf[nt2]);
                #pragma unroll
                for (int mt = 0; mt < 2; mt++)
                    #pragma unroll
                    for (int nt2 = 0; nt2 < 4; nt2++) {
                        mma16816(c[mt][nt2 * 2 + 0], af[mt], &bf[nt2][0]);
                        mma16816(c[mt][nt2 * 2 + 1], af[mt], &bf[nt2][2]);
                    }
            }
        }
        __syncthreads();
    }

    // ---- C regs -> smem staging (for coalesced fused epilogue) ----
    float* stg = (float*)sbase;        // 128 x 132 floats
    #pragma unroll
    for (int mt = 0; mt < 2; mt++) {
        #pragma unroll
        for (int nt = 0; nt < 8; nt++) {
            int r0 = wm * 32 + mt * 16 + (lane >> 2);
            int col = wn * 64 + nt * 8 + (lane & 3) * 2;
            *(float2*)&stg[r0 * 132 + col]       = make_float2(c[mt][nt][0], c[mt][nt][1]);
            *(float2*)&stg[(r0 + 8) * 132 + col] = make_float2(c[mt][nt][2], c[mt][nt][3]);
        }
    }
    __syncthreads();

    #pragma unroll
    for (int p = 0; p < 16; p++) {
        int f = tid + p * 256;
        int row = f >> 5;
        int c4 = f & 31;
        int m = m0 + row;
        if (m >= N_NODES) continue;
        int col = c4 * 4;
        int gcol = n0 + col;
        float4 v = *(float4*)&stg[row * 132 + col];
        float4 b4 = __ldg((const float4*)(bias + gcol));
        float v0 = v.x + b4.x, v1 = v.y + b4.y, v2 = v.z + b4.z, v3 = v.w + b4.w;
        size_t off = (size_t)m * H + gcol;
        if (MODE == 0) {
            float4 vv = make_float4(v0, v1, v2, v3);
            *(float4*)(OA + off) = vv;
            *(float4*)(OB + off) = vv;
            uint2 hh = pack4(v0, v1, v2, v3);
            uint2 ll = pack4(bflo(v0), bflo(v1), bflo(v2), bflo(v3));
            *(uint2*)(OAh + off) = hh; *(uint2*)(OAl + off) = ll;
            *(uint2*)(OBh + off) = hh; *(uint2*)(OBl + off) = ll;
        }
        if (MODE == 1) {
            float dv = g_degf[m];
            float4 b2v = __ldg((const float4*)(bias2 + gcol));
            v0 = fmaxf(v0 + dv * b2v.x, 0.f);
            v1 = fmaxf(v1 + dv * b2v.y, 0.f);
            v2 = fmaxf(v2 + dv * b2v.z, 0.f);
            v3 = fmaxf(v3 + dv * b2v.w, 0.f);
            *(uint2*)(OAh + off) = pack4(v0, v1, v2, v3);
            *(uint2*)(OAl + off) = pack4(bflo(v0), bflo(v1), bflo(v2), bflo(v3));
        }
        if (MODE == 2) {
            v0 = 1.f / (1.f + expf(-v0));
            v1 = 1.f / (1.f + expf(-v1));
            v2 = 1.f / (1.f + expf(-v2));
            v3 = 1.f / (1.f + expf(-v3));
            *(float4*)(OA + off) = make_float4(v0, v1, v2, v3);
            float4 xv = __ldg((const float4*)(Xin + off));
            *(float4*)(OB + off) = make_float4(v0 * xv.x, v1 * xv.y, v2 * xv.z, v3 * xv.w);
        }
        if (MODE == 3) {
            v0 = fmaxf(v0, 0.f); v1 = fmaxf(v1, 0.f);
            v2 = fmaxf(v2, 0.f); v3 = fmaxf(v3, 0.f);
            *(float4*)(OA + off) = make_float4(v0, v1, v2, v3);
            *(uint2*)(OAh + off) = pack4(v0, v1, v2, v3);
            *(uint2*)(OAl + off) = pack4(bflo(v0), bflo(v1), bflo(v2), bflo(v3));
            float4 mv = __ldg((const float4*)(Mask + off));
            float t0 = v0 * mv.x, t1 = v1 * mv.y, t2 = v2 * mv.z, t3 = v3 * mv.w;
            *(float4*)(OB + off) = make_float4(t0, t1, t2, t3);
            *(uint2*)(OBh + off) = pack4(t0, t1, t2, t3);
            *(uint2*)(OBl + off) = pack4(bflo(t0), bflo(t1), bflo(t2), bflo(t3));
            *(float4*)(Dout + (size_t)m * (NLAYERS * H) + gcol) = make_float4(v0, v1, v2, v3);
        }
    }
}

__global__ void k_tail(float* p, int n) {
    int i = blockIdx.x * blockDim.x + threadIdx.x;
    if (i < n) p[i] = 1.0f;
}

// ---------------- launch ----------------
extern "C" void kernel_launch(void* const* d_in, const int* in_sizes, int n_in,
                              void* d_out, int out_size)
{
    (void)in_sizes; (void)n_in;
    const int*   edge   = (const int*)  d_in[1];
    const float* esm    = (const float*)d_in[2];
    const float* lin0_W = (const float*)d_in[4];
    const float* lin0_b = (const float*)d_in[5];
    const float* wc_W1  = (const float*)d_in[6];
    const float* wc_b1  = (const float*)d_in[7];
    const float* wc_W2  = (const float*)d_in[8];
    const float* wc_b2  = (const float*)d_in[9];
    const float* wc_W3  = (const float*)d_in[10];
    const float* wc_b3  = (const float*)d_in[11];
    const float* sc_Wn  = (const float*)d_in[12];
    const float* sc_bn  = (const float*)d_in[13];
    const float* sc_Wr  = (const float*)d_in[14];
    float* out = (float*)d_out;

    const int* src = edge;
    const int* dst = edge + N_EDGES;

    cudaFuncSetAttribute(k_mma<0>, cudaFuncAttributeMaxDynamicSharedMemorySize, DSMEM_BYTES);
    cudaFuncSetAttribute(k_mma<1>, cudaFuncAttributeMaxDynamicSharedMemorySize, DSMEM_BYTES);
    cudaFuncSetAttribute(k_mma<2>, cudaFuncAttributeMaxDynamicSharedMemorySize, DSMEM_BYTES);
    cudaFuncSetAttribute(k_mma<3>, cudaFuncAttributeMaxDynamicSharedMemorySize, DSMEM_BYTES);

    float *pX0, *pX1, *pM, *pT;
    bf16 *pX0h, *pX0l, *pX1h, *pX1l, *pTh, *pTl, *pSh, *pSl, *pHbh, *pHbl;
    bf16 *pEh, *pEl, *pW0h, *pW0l, *pWth, *pWtl;
    cudaGetSymbolAddress((void**)&pX0, g_X0);
    cudaGetSymbolAddress((void**)&pX1, g_X1);
    cudaGetSymbolAddress((void**)&pM,  g_M);
    cudaGetSymbolAddress((void**)&pT,  g_T);
    cudaGetSymbolAddress((void**)&pX0h, g_X0h); cudaGetSymbolAddress((void**)&pX0l, g_X0l);
    cudaGetSymbolAddress((void**)&pX1h, g_X1h); cudaGetSymbolAddress((void**)&pX1l, g_X1l);
    cudaGetSymbolAddress((void**)&pTh, g_Th);   cudaGetSymbolAddress((void**)&pTl, g_Tl);
    cudaGetSymbolAddress((void**)&pSh, g_Sh);   cudaGetSymbolAddress((void**)&pSl, g_Sl);
    cudaGetSymbolAddress((void**)&pHbh, g_Hbh); cudaGetSymbolAddress((void**)&pHbl, g_Hbl);
    cudaGetSymbolAddress((void**)&pEh, g_Eh);   cudaGetSymbolAddress((void**)&pEl, g_El);
    cudaGetSymbolAddress((void**)&pW0h, g_W0th);cudaGetSymbolAddress((void**)&pW0l, g_W0tl);
    cudaGetSymbolAddress((void**)&pWth, g_Wth); cudaGetSymbolAddress((void**)&pWtl, g_Wtl);

    // CSR build
    k_zero_deg<<<(N_NODES + 255) / 256, 256>>>();
    k_hist    <<<(N_EDGES + 255) / 256, 256>>>(dst);
    int nblk = (N_NODES + 1023) / 1024;
    k_scan_block<<<nblk, 1024>>>();
    k_scan_sums <<<1, 32>>>(nblk);
    k_finalize  <<<nblk, 1024>>>();
    k_fill_csr  <<<(N_EDGES + 255) / 256, 256>>>(src, dst);

    // input / weight splits
    k_split<<<(N_NODES * F_IN / 4 + 255) / 256, 256>>>((const float4*)esm, (uint2*)pEh, (uint2*)pEl, N_NODES * F_IN / 4);
    k_splitT0<<<(F_IN * H + 255) / 256, 256>>>(lin0_W);
    k_splitW<<<(5 * NLAYERS * H * H + 255) / 256, 256>>>(wc_W1, wc_W2, wc_W3, sc_Wn, sc_Wr);

    dim3 ggrid((N_NODES + 127) / 128, 2);   // 391 x 2
    dim3 agrid((N_NODES + 3) / 4);          // 12500

    // lin0: x = esm @ W0 + b0 ; T = x
    k_mma<0><<<ggrid, 256, DSMEM_BYTES>>>(
        pEh, pEl, F_IN, pEh, pEl, 0,
        pW0h, pW0l, pW0h, pW0l,
        lin0_b, nullptr,
        pX0, pX0h, pX0l, pT, pTh, pTl,
        nullptr, nullptr, nullptr);

    float* xc = pX0;  bf16* xch = pX0h; bf16* xcl = pX0l;
    float* xn = pX1;  bf16* xnh = pX1h; bf16* xnl = pX1l;
    for (int i = 0; i < NLAYERS; i++) {
        bf16* Wt1h = pWth + (size_t)(i * 5 + 0) * 65536; bf16* Wt1l = pWtl + (size_t)(i * 5 + 0) * 65536;
        bf16* Wt2h = pWth + (size_t)(i * 5 + 1) * 65536; bf16* Wt2l = pWtl + (size_t)(i * 5 + 1) * 65536;
        bf16* Wt3h = pWth + (size_t)(i * 5 + 2) * 65536; bf16* Wt3l = pWtl + (size_t)(i * 5 + 2) * 65536;
        bf16* Wtnh = pWth + (size_t)(i * 5 + 3) * 65536; bf16* Wtnl = pWtl + (size_t)(i * 5 + 3) * 65536;
        bf16* Wtrh = pWth + (size_t)(i * 5 + 4) * 65536; bf16* Wtrl = pWtl + (size_t)(i * 5 + 4) * 65536;
        const float* b1 = wc_b1 + (size_t)i * H;
        const float* b2 = wc_b2 + (size_t)i * H;
        const float* b3 = wc_b3 + (size_t)i * H;
        const float* bn = sc_bn + (size_t)i * H;

        // S = A . xm
        k_aggregate<<<agrid, 256>>>((const float4*)pT, (uint2*)pSh, (uint2*)pSl);
        // h = relu(S@W2 + deg*b2 + xm@W1 + b1)
        k_mma<1><<<ggrid, 256, DSMEM_BYTES>>>(
            pSh, pSl, H, pTh, pTl, H,
            Wt2h, Wt2l, Wt1h, Wt1l,
            b1, b2,
            nullptr, pHbh, pHbl, nullptr, nullptr, nullptr,
            nullptr, nullptr, nullptr);
        // mask = sigmoid(h@W3 + b3) ; xg = x * mask
        k_mma<2><<<ggrid, 256, DSMEM_BYTES>>>(
            pHbh, pHbl, H, pHbh, pHbl, 0,
            Wt3h, Wt3l, Wt3h, Wt3l,
            b3, nullptr,
            pM, nullptr, nullptr, pT, nullptr, nullptr,
            xc, nullptr, nullptr);
        // S2 = A . xg
        k_aggregate<<<agrid, 256>>>((const float4*)pT, (uint2*)pSh, (uint2*)pSl);
        // x' = relu(S2@Wn + bn + x@Wr) ; xm_next = x'*mask ; dout block i
        k_mma<3><<<ggrid, 256, DSMEM_BYTES>>>(
            pSh, pSl, H, xch, xcl, H,
            Wtnh, Wtnl, Wtrh, Wtrl,
            bn, nullptr,
            xn, xnh, xnl, pT, pTh, pTl,
            nullptr, pM, out + (size_t)i * H);

        float* tf = xc; xc = xn; xn = tf;
        bf16* th = xch; xch = xnh; xnh = th;
        bf16* tl = xcl; xcl = xnl; xnl = tl;
    }

    long long tail = (long long)out_size - (long long)N_NODES * (NLAYERS * H);
    if (tail > 0) {
        k_tail<<<(int)((tail + 255) / 256), 256>>>(out + (size_t)N_NODES * (NLAYERS * H), (int)tail);
    }
}

// round 4
// speedup vs baseline: 1.7486x; 1.1905x over previous
#include <cuda_runtime.h>
#include <cuda_bf16.h>
#include <math.h>
#include <stdint.h>

#define N_NODES 50000
#define N_EDGES 800000
#define H 256
#define F_IN 1280
#define NLAYERS 4

typedef __nv_bfloat16 bf16;

// ---------------- scratch (device globals; no allocation) ----------------
__device__ __align__(256) float g_X0[N_NODES * H];
__device__ __align__(256) float g_X1[N_NODES * H];
__device__ __align__(256) float g_T [N_NODES * H];   // xm / xg (fp32, aggregation input)
__device__ __align__(256) float g_M [N_NODES * H];   // mask
__device__ __align__(256) bf16  g_X0h[N_NODES * H], g_X0l[N_NODES * H];
__device__ __align__(256) bf16  g_X1h[N_NODES * H], g_X1l[N_NODES * H];
__device__ __align__(256) bf16  g_Th [N_NODES * H], g_Tl [N_NODES * H];
__device__ __align__(256) bf16  g_Sh [N_NODES * H], g_Sl [N_NODES * H];
__device__ __align__(256) bf16  g_Hbh[N_NODES * H], g_Hbl[N_NODES * H];
__device__ __align__(256) bf16  g_Eh [N_NODES * F_IN], g_El[N_NODES * F_IN];
__device__ __align__(256) bf16  g_W0th[H * F_IN], g_W0tl[H * F_IN];      // lin0_W transposed [n][k]
__device__ __align__(256) bf16  g_Wth[NLAYERS * 5 * H * H];              // per (layer,type), [n][k]
__device__ __align__(256) bf16  g_Wtl[NLAYERS * 5 * H * H];
__device__ int   g_deg [N_NODES];
__device__ int   g_ptr [N_NODES];
__device__ int   g_fill[N_NODES];
__device__ int   g_csr [N_EDGES];
__device__ float g_degf[N_NODES];
__device__ int   g_bsum[64];

// ---------------- helpers ----------------
__device__ __forceinline__ uint32_t smem_u32(const void* p) {
    uint32_t a;
    asm("{ .reg .u64 t; cvta.to.shared.u64 t, %1; cvt.u32.u64 %0, t; }" : "=r"(a) : "l"(p));
    return a;
}
__device__ __forceinline__ void cp16(uint32_t saddr, const void* g) {
    asm volatile("cp.async.cg.shared.global [%0], [%1], 16;" :: "r"(saddr), "l"(g));
}
__device__ __forceinline__ void cp_commit() {
    asm volatile("cp.async.commit_group;" ::: "memory");
}
template<int n>
__device__ __forceinline__ void cp_wait() {
    asm volatile("cp.async.wait_group %0;" :: "n"(n) : "memory");
}
__device__ __forceinline__ void ldm4(uint32_t a, uint32_t* r) {
    asm volatile("ldmatrix.sync.aligned.m8n8.x4.shared.b16 {%0,%1,%2,%3}, [%4];"
        : "=r"(r[0]), "=r"(r[1]), "=r"(r[2]), "=r"(r[3]) : "r"(a));
}
__device__ __forceinline__ void mma16816(float* c, const uint32_t* a, const uint32_t* b) {
    asm volatile("mma.sync.aligned.m16n8k16.row.col.f32.bf16.bf16.f32 "
        "{%0,%1,%2,%3}, {%4,%5,%6,%7}, {%8,%9}, {%0,%1,%2,%3};"
        : "+f"(c[0]), "+f"(c[1]), "+f"(c[2]), "+f"(c[3])
        : "r"(a[0]), "r"(a[1]), "r"(a[2]), "r"(a[3]), "r"(b[0]), "r"(b[1]));
}

__device__ __forceinline__ unsigned pack2(float a, float b) {
    __nv_bfloat162 t = __floats2bfloat162_rn(a, b);
    return *(unsigned*)&t;
}
__device__ __forceinline__ uint2 pack4(float a, float b, float c, float d) {
    uint2 r; r.x = pack2(a, b); r.y = pack2(c, d); return r;
}
__device__ __forceinline__ float bflo(float a) {
    return a - __bfloat162float(__float2bfloat16(a));
}

// ---------------- CSR build ----------------
__global__ void k_zero_deg() {
    int i = blockIdx.x * blockDim.x + threadIdx.x;
    if (i < N_NODES) g_deg[i] = 0;
}
__global__ void k_hist(const int* __restrict__ dst) {
    int e = blockIdx.x * blockDim.x + threadIdx.x;
    if (e < N_EDGES) atomicAdd(&g_deg[dst[e]], 1);
}
__global__ void k_scan_block() {
    __shared__ int sh[1024];
    int i = blockIdx.x * 1024 + threadIdx.x;
    int v = (i < N_NODES) ? g_deg[i] : 0;
    sh[threadIdx.x] = v;
    __syncthreads();
    for (int off = 1; off < 1024; off <<= 1) {
        int t = (threadIdx.x >= off) ? sh[threadIdx.x - off] : 0;
        __syncthreads();
        sh[threadIdx.x] += t;
        __syncthreads();
    }
    if (i < N_NODES) g_ptr[i] = sh[threadIdx.x] - v;
    if (threadIdx.x == 1023) g_bsum[blockIdx.x] = sh[1023];
}
__global__ void k_scan_sums(int nb) {
    if (threadIdx.x == 0 && blockIdx.x == 0) {
        int run = 0;
        for (int b = 0; b < nb; b++) { int t = g_bsum[b]; g_bsum[b] = run; run += t; }
    }
}
__global__ void k_finalize() {
    int i = blockIdx.x * 1024 + threadIdx.x;
    if (i < N_NODES) {
        int p = g_ptr[i] + g_bsum[blockIdx.x];
        g_ptr[i]  = p;
        g_fill[i] = p;
        g_degf[i] = (float)g_deg[i];
    }
}
__global__ void k_fill_csr(const int* __restrict__ src, const int* __restrict__ dst) {
    int e = blockIdx.x * blockDim.x + threadIdx.x;
    if (e < N_EDGES) {
        int p = atomicAdd(&g_fill[dst[e]], 1);
        g_csr[p] = src[e];
    }
}

// ---------------- splits ----------------
__global__ void k_split(const float4* __restrict__ src, uint2* __restrict__ hi,
                        uint2* __restrict__ lo, int n4) {
    int i = blockIdx.x * blockDim.x + threadIdx.x;
    if (i < n4) {
        float4 v = __ldg(&src[i]);
        hi[i] = pack4(v.x, v.y, v.z, v.w);
        lo[i] = pack4(bflo(v.x), bflo(v.y), bflo(v.z), bflo(v.w));
    }
}
__global__ void k_splitT0(const float* __restrict__ W) {
    int i = blockIdx.x * blockDim.x + threadIdx.x;
    if (i < F_IN * H) {
        int k = i >> 8, n = i & 255;
        float v = __ldg(&W[i]);
        g_W0th[n * F_IN + k] = __float2bfloat16(v);
        g_W0tl[n * F_IN + k] = __float2bfloat16(bflo(v));
    }
}
__global__ void k_splitW(const float* __restrict__ W1, const float* __restrict__ W2,
                         const float* __restrict__ W3, const float* __restrict__ Wn,
                         const float* __restrict__ Wr) {
    int i = blockIdx.x * blockDim.x + threadIdx.x;
    const int per_type = NLAYERS * H * H;
    if (i < 5 * per_type) {
        int t = i / per_type;
        int r = i - t * per_type;
        int layer = r >> 16;
        int idx = r & 65535;
        int k = idx >> 8, n = idx & 255;
        const float* src = (t == 0) ? W1 : (t == 1) ? W2 : (t == 2) ? W3 : (t == 3) ? Wn : Wr;
        float v = __ldg(&src[r]);
        size_t d = (size_t)(layer * 5 + t) * 65536 + n * 256 + k;
        g_Wth[d] = __float2bfloat16(v);
        g_Wtl[d] = __float2bfloat16(bflo(v));
    }
}

// ---------------- CSR gather-aggregate -> bf16 hi/lo ----------------
__global__ void k_aggregate(const float4* __restrict__ Xin,
                            uint2* __restrict__ Sh, uint2* __restrict__ Sl) {
    int node = blockIdx.x * 4 + (threadIdx.x >> 6);
    int lane = threadIdx.x & 63;
    if (node >= N_NODES) return;
    int s = g_ptr[node];
    int d = g_deg[node];
    float4 acc = make_float4(0.f, 0.f, 0.f, 0.f);
    for (int e = s; e < s + d; e++) {
        int u = __ldg(&g_csr[e]);
        float4 v = __ldg(&Xin[(size_t)u * 64 + lane]);
        acc.x += v.x; acc.y += v.y; acc.z += v.z; acc.w += v.w;
    }
    size_t o = (size_t)node * 64 + lane;
    Sh[o] = pack4(acc.x, acc.y, acc.z, acc.w);
    Sl[o] = pack4(bflo(acc.x), bflo(acc.y), bflo(acc.z), bflo(acc.w));
}

// ---------------- mma.sync GEMM: D[128 x 128] per CTA, 3-term bf16 split ----------------
// BK=32 stage; smem per matrix: 128 rows x 40 elems (32 + 8 pad) x 2B = 10240 B
#define ROWB 80             // 40 elements * 2B
#define OFF_AH 0
#define OFF_AL 10240
#define OFF_BH 20480
#define OFF_BL 30720
#define STAGE_BYTES 40960
#define DSMEM_BYTES (2 * STAGE_BYTES + 1024)

struct Tiles {
    const bf16 *A0h, *A0l, *A1h, *A1l;
    const bf16 *B0h, *B0l, *B1h, *B1l;
    int K0, K1;
};

__device__ __forceinline__ void load_stage_async(uint32_t st, int tid, int m0, int n0,
                                                 int kt, const Tiles& t) {
    const bf16 *Ah, *Al, *Bh, *Bl; int K, kl;
    if (kt < t.K0) { Ah = t.A0h; Al = t.A0l; Bh = t.B0h; Bl = t.B0l; K = t.K0; kl = kt; }
    else           { Ah = t.A1h; Al = t.A1l; Bh = t.B1h; Bl = t.B1l; K = t.K1; kl = kt - t.K0; }
    #pragma unroll
    for (int l = 0; l < 2; l++) {
        int f = tid + l * 256;
        int r = f >> 2, q = f & 3;
        int m = m0 + r; if (m >= N_NODES) m = N_NODES - 1;
        size_t g = (size_t)m * K + kl + q * 8;
        uint32_t s = st + r * ROWB + q * 16;
        cp16(s + OFF_AH, Ah + g);
        cp16(s + OFF_AL, Al + g);
    }
    #pragma unroll
    for (int l = 0; l < 2; l++) {
        int f = tid + l * 256;
        int r = f >> 2, q = f & 3;
        size_t g = (size_t)(n0 + r) * K + kl + q * 8;
        uint32_t s = st + r * ROWB + q * 16;
        cp16(s + OFF_BH, Bh + g);
        cp16(s + OFF_BL, Bl + g);
    }
}

// MODE 0 (lin0): v = acc+b       -> OA,OAh,OAl and OB,OBh,OBl (duplicate)
// MODE 1 (h)   : v = relu(acc+b1+deg*b2) -> OAh,OAl
// MODE 2 (mask): mk=sigmoid(acc+b3) -> OA=mask; OB = mk*Xin (xg, fp32 only)
// MODE 3 (x')  : v = relu(acc+bn) -> OA,OAh,OAl; OB=v*Mask,OBh,OBl; Dout
template<int MODE>
__global__ void __launch_bounds__(256, 2) k_mma(
    const bf16* A0h, const bf16* A0l, int K0,
    const bf16* A1h, const bf16* A1l, int K1,
    const bf16* B0h, const bf16* B0l,
    const bf16* B1h, const bf16* B1l,
    const float* __restrict__ bias, const float* __restrict__ bias2,
    float* __restrict__ OA, bf16* __restrict__ OAh, bf16* __restrict__ OAl,
    float* __restrict__ OB, bf16* __restrict__ OBh, bf16* __restrict__ OBl,
    const float* __restrict__ Xin, const float* __restrict__ Mask,
    float* __restrict__ Dout)
{
    extern __shared__ char dsm_raw[];
    char* sbase = (char*)(((uintptr_t)dsm_raw + 1023) & ~(uintptr_t)1023);
    const uint32_t sb32 = smem_u32(sbase);

    const int tid = threadIdx.x;
    const int wid = tid >> 5;
    const int lane = tid & 31;
    const int wm = wid & 3;     // 4 m-groups of 32 rows
    const int wn = wid >> 2;    // 2 n-groups of 64 cols
    const int m0 = blockIdx.x * 128;
    const int n0 = blockIdx.y * 128;

    Tiles t; t.A0h = A0h; t.A0l = A0l; t.A1h = A1h; t.A1l = A1l;
    t.B0h = B0h; t.B0l = B0l; t.B1h = B1h; t.B1l = B1l; t.K0 = K0; t.K1 = K1;

    float c[2][8][4];
    #pragma unroll
    for (int i = 0; i < 2; i++)
        #pragma unroll
        for (int j = 0; j < 8; j++)
            #pragma unroll
            for (int q = 0; q < 4; q++) c[i][j][q] = 0.f;

    const int nIter = (K0 + K1) >> 5;

    load_stage_async(sb32, tid, m0, n0, 0, t);
    cp_commit();

    // fragment address bases (lane-dependent, stage-relative)
    const uint32_t aAddrBase = (wm * 32 + (lane & 15)) * ROWB + (lane >> 4) * 16;
    const uint32_t bAddrBase = (wn * 64 + (lane & 7) + ((lane >> 4) & 1) * 8) * ROWB
                             + ((lane >> 3) & 1) * 16;

    for (int it = 0; it < nIter; ++it) {
        const uint32_t stu = sb32 + (it & 1) * STAGE_BYTES;
        if (it + 1 < nIter) {
            load_stage_async(sb32 + ((it + 1) & 1) * STAGE_BYTES, tid, m0, n0, (it + 1) << 5, t);
            cp_commit();
            cp_wait<1>();
        } else {
            cp_wait<0>();
        }
        __syncthreads();

        #pragma unroll
        for (int term = 0; term < 3; term++) {
            const uint32_t aOff = stu + ((term < 2) ? OFF_AH : OFF_AL);
            const uint32_t bOff = stu + ((term == 1) ? OFF_BL : OFF_BH);
            #pragma unroll
            for (int ks = 0; ks < 2; ks++) {
                const uint32_t kb = ks * 32;   // 16 elements * 2B
                uint32_t af[2][4];
                #pragma unroll
                for (int mt = 0; mt < 2; mt++)
                    ldm4(aOff + aAddrBase + mt * (16 * ROWB) + kb, af[mt]);
                uint32_t bf[4][4];
                #pragma unroll
                for (int nt2 = 0; nt2 < 4; nt2++)
                    ldm4(bOff + bAddrBase + nt2 * (16 * ROWB) + kb, bf[nt2]);
                #pragma unroll
                for (int mt = 0; mt < 2; mt++)
                    #pragma unroll
                    for (int nt2 = 0; nt2 < 4; nt2++) {
                        mma16816(c[mt][nt2 * 2 + 0], af[mt], &bf[nt2][0]);
                        mma16816(c[mt][nt2 * 2 + 1], af[mt], &bf[nt2][2]);
                    }
            }
        }
        __syncthreads();
    }

    // ---- C regs -> smem staging, two 64-col halves (smem = 128 x 68 floats) ----
    float* stg = (float*)sbase;
    #pragma unroll
    for (int hh = 0; hh < 2; hh++) {
        if (wn == hh) {
            #pragma unroll
            for (int mt = 0; mt < 2; mt++) {
                #pragma unroll
                for (int nt = 0; nt < 8; nt++) {
                    int r0 = wm * 32 + mt * 16 + (lane >> 2);
                    int col = nt * 8 + (lane & 3) * 2;
                    *(float2*)&stg[r0 * 68 + col]       = make_float2(c[mt][nt][0], c[mt][nt][1]);
                    *(float2*)&stg[(r0 + 8) * 68 + col] = make_float2(c[mt][nt][2], c[mt][nt][3]);
                }
            }
        }
        __syncthreads();

        #pragma unroll
        for (int p = 0; p < 8; p++) {
            int f = tid + p * 256;
            int row = f >> 4;
            int c4 = f & 15;
            int m = m0 + row;
            if (m < N_NODES) {
                int col = c4 * 4;
                int gcol = n0 + hh * 64 + col;
                float4 v = *(float4*)&stg[row * 68 + col];
                float4 b4 = __ldg((const float4*)(bias + gcol));
                float v0 = v.x + b4.x, v1 = v.y + b4.y, v2 = v.z + b4.z, v3 = v.w + b4.w;
                size_t off = (size_t)m * H + gcol;
                if (MODE == 0) {
                    float4 vv = make_float4(v0, v1, v2, v3);
                    *(float4*)(OA + off) = vv;
                    *(float4*)(OB + off) = vv;
                    uint2 hhh = pack4(v0, v1, v2, v3);
                    uint2 lll = pack4(bflo(v0), bflo(v1), bflo(v2), bflo(v3));
                    *(uint2*)(OAh + off) = hhh; *(uint2*)(OAl + off) = lll;
                    *(uint2*)(OBh + off) = hhh; *(uint2*)(OBl + off) = lll;
                }
                if (MODE == 1) {
                    float dv = g_degf[m];
                    float4 b2v = __ldg((const float4*)(bias2 + gcol));
                    v0 = fmaxf(v0 + dv * b2v.x, 0.f);
                    v1 = fmaxf(v1 + dv * b2v.y, 0.f);
                    v2 = fmaxf(v2 + dv * b2v.z, 0.f);
                    v3 = fmaxf(v3 + dv * b2v.w, 0.f);
                    *(uint2*)(OAh + off) = pack4(v0, v1, v2, v3);
                    *(uint2*)(OAl + off) = pack4(bflo(v0), bflo(v1), bflo(v2), bflo(v3));
                }
                if (MODE == 2) {
                    v0 = 1.f / (1.f + expf(-v0));
                    v1 = 1.f / (1.f + expf(-v1));
                    v2 = 1.f / (1.f + expf(-v2));
                    v3 = 1.f / (1.f + expf(-v3));
                    *(float4*)(OA + off) = make_float4(v0, v1, v2, v3);
                    float4 xv = __ldg((const float4*)(Xin + off));
                    *(float4*)(OB + off) = make_float4(v0 * xv.x, v1 * xv.y, v2 * xv.z, v3 * xv.w);
                }
                if (MODE == 3) {
                    v0 = fmaxf(v0, 0.f); v1 = fmaxf(v1, 0.f);
                    v2 = fmaxf(v2, 0.f); v3 = fmaxf(v3, 0.f);
                    *(float4*)(OA + off) = make_float4(v0, v1, v2, v3);
                    *(uint2*)(OAh + off) = pack4(v0, v1, v2, v3);
                    *(uint2*)(OAl + off) = pack4(bflo(v0), bflo(v1), bflo(v2), bflo(v3));
                    float4 mv = __ldg((const float4*)(Mask + off));
                    float t0 = v0 * mv.x, t1 = v1 * mv.y, t2 = v2 * mv.z, t3 = v3 * mv.w;
                    *(float4*)(OB + off) = make_float4(t0, t1, t2, t3);
                    *(uint2*)(OBh + off) = pack4(t0, t1, t2, t3);
                    *(uint2*)(OBl + off) = pack4(bflo(t0), bflo(t1), bflo(t2), bflo(t3));
                    *(float4*)(Dout + (size_t)m * (NLAYERS * H) + gcol) = make_float4(v0, v1, v2, v3);
                }
            }
        }
        __syncthreads();
    }
}

__global__ void k_tail(float* p, int n) {
    int i = blockIdx.x * blockDim.x + threadIdx.x;
    if (i < n) p[i] = 1.0f;
}

// ---------------- launch ----------------
extern "C" void kernel_launch(void* const* d_in, const int* in_sizes, int n_in,
                              void* d_out, int out_size)
{
    (void)in_sizes; (void)n_in;
    const int*   edge   = (const int*)  d_in[1];
    const float* esm    = (const float*)d_in[2];
    const float* lin0_W = (const float*)d_in[4];
    const float* lin0_b = (const float*)d_in[5];
    const float* wc_W1  = (const float*)d_in[6];
    const float* wc_b1  = (const float*)d_in[7];
    const float* wc_W2  = (const float*)d_in[8];
    const float* wc_b2  = (const float*)d_in[9];
    const float* wc_W3  = (const float*)d_in[10];
    const float* wc_b3  = (const float*)d_in[11];
    const float* sc_Wn  = (const float*)d_in[12];
    const float* sc_bn  = (const float*)d_in[13];
    const float* sc_Wr  = (const float*)d_in[14];
    float* out = (float*)d_out;

    const int* src = edge;
    const int* dst = edge + N_EDGES;

    cudaFuncSetAttribute(k_mma<0>, cudaFuncAttributeMaxDynamicSharedMemorySize, DSMEM_BYTES);
    cudaFuncSetAttribute(k_mma<1>, cudaFuncAttributeMaxDynamicSharedMemorySize, DSMEM_BYTES);
    cudaFuncSetAttribute(k_mma<2>, cudaFuncAttributeMaxDynamicSharedMemorySize, DSMEM_BYTES);
    cudaFuncSetAttribute(k_mma<3>, cudaFuncAttributeMaxDynamicSharedMemorySize, DSMEM_BYTES);

    float *pX0, *pX1, *pM, *pT;
    bf16 *pX0h, *pX0l, *pX1h, *pX1l, *pTh, *pTl, *pSh, *pSl, *pHbh, *pHbl;
    bf16 *pEh, *pEl, *pW0h, *pW0l, *pWth, *pWtl;
    cudaGetSymbolAddress((void**)&pX0, g_X0);
    cudaGetSymbolAddress((void**)&pX1, g_X1);
    cudaGetSymbolAddress((void**)&pM,  g_M);
    cudaGetSymbolAddress((void**)&pT,  g_T);
    cudaGetSymbolAddress((void**)&pX0h, g_X0h); cudaGetSymbolAddress((void**)&pX0l, g_X0l);
    cudaGetSymbolAddress((void**)&pX1h, g_X1h); cudaGetSymbolAddress((void**)&pX1l, g_X1l);
    cudaGetSymbolAddress((void**)&pTh, g_Th);   cudaGetSymbolAddress((void**)&pTl, g_Tl);
    cudaGetSymbolAddress((void**)&pSh, g_Sh);   cudaGetSymbolAddress((void**)&pSl, g_Sl);
    cudaGetSymbolAddress((void**)&pHbh, g_Hbh); cudaGetSymbolAddress((void**)&pHbl, g_Hbl);
    cudaGetSymbolAddress((void**)&pEh, g_Eh);   cudaGetSymbolAddress((void**)&pEl, g_El);
    cudaGetSymbolAddress((void**)&pW0h, g_W0th);cudaGetSymbolAddress((void**)&pW0l, g_W0tl);
    cudaGetSymbolAddress((void**)&pWth, g_Wth); cudaGetSymbolAddress((void**)&pWtl, g_Wtl);

    // CSR build
    k_zero_deg<<<(N_NODES + 255) / 256, 256>>>();
    k_hist    <<<(N_EDGES + 255) / 256, 256>>>(dst);
    int nblk = (N_NODES + 1023) / 1024;
    k_scan_block<<<nblk, 1024>>>();
    k_scan_sums <<<1, 32>>>(nblk);
    k_finalize  <<<nblk, 1024>>>();
    k_fill_csr  <<<(N_EDGES + 255) / 256, 256>>>(src, dst);

    // input / weight splits
    k_split<<<(N_NODES * F_IN / 4 + 255) / 256, 256>>>((const float4*)esm, (uint2*)pEh, (uint2*)pEl, N_NODES * F_IN / 4);
    k_splitT0<<<(F_IN * H + 255) / 256, 256>>>(lin0_W);
    k_splitW<<<(5 * NLAYERS * H * H + 255) / 256, 256>>>(wc_W1, wc_W2, wc_W3, sc_Wn, sc_Wr);

    dim3 ggrid((N_NODES + 127) / 128, 2);   // 391 x 2
    dim3 agrid((N_NODES + 3) / 4);          // 12500

    // lin0: x = esm @ W0 + b0 ; T = x
    k_mma<0><<<ggrid, 256, DSMEM_BYTES>>>(
        pEh, pEl, F_IN, pEh, pEl, 0,
        pW0h, pW0l, pW0h, pW0l,
        lin0_b, nullptr,
        pX0, pX0h, pX0l, pT, pTh, pTl,
        nullptr, nullptr, nullptr);

    float* xc = pX0;  bf16* xch = pX0h; bf16* xcl = pX0l;
    float* xn = pX1;  bf16* xnh = pX1h; bf16* xnl = pX1l;
    for (int i = 0; i < NLAYERS; i++) {
        bf16* Wt1h = pWth + (size_t)(i * 5 + 0) * 65536; bf16* Wt1l = pWtl + (size_t)(i * 5 + 0) * 65536;
        bf16* Wt2h = pWth + (size_t)(i * 5 + 1) * 65536; bf16* Wt2l = pWtl + (size_t)(i * 5 + 1) * 65536;
        bf16* Wt3h = pWth + (size_t)(i * 5 + 2) * 65536; bf16* Wt3l = pWtl + (size_t)(i * 5 + 2) * 65536;
        bf16* Wtnh = pWth + (size_t)(i * 5 + 3) * 65536; bf16* Wtnl = pWtl + (size_t)(i * 5 + 3) * 65536;
        bf16* Wtrh = pWth + (size_t)(i * 5 + 4) * 65536; bf16* Wtrl = pWtl + (size_t)(i * 5 + 4) * 65536;
        const float* b1 = wc_b1 + (size_t)i * H;
        const float* b2 = wc_b2 + (size_t)i * H;
        const float* b3 = wc_b3 + (size_t)i * H;
        const float* bn = sc_bn + (size_t)i * H;

        // S = A . xm
        k_aggregate<<<agrid, 256>>>((const float4*)pT, (uint2*)pSh, (uint2*)pSl);
        // h = relu(S@W2 + deg*b2 + xm@W1 + b1)
        k_mma<1><<<ggrid, 256, DSMEM_BYTES>>>(
            pSh, pSl, H, pTh, pTl, H,
            Wt2h, Wt2l, Wt1h, Wt1l,
            b1, b2,
            nullptr, pHbh, pHbl, nullptr, nullptr, nullptr,
            nullptr, nullptr, nullptr);
        // mask = sigmoid(h@W3 + b3) ; xg = x * mask
        k_mma<2><<<ggrid, 256, DSMEM_BYTES>>>(
            pHbh, pHbl, H, pHbh, pHbl, 0,
            Wt3h, Wt3l, Wt3h, Wt3l,
            b3, nullptr,
            pM, nullptr, nullptr, pT, nullptr, nullptr,
            xc, nullptr, nullptr);
        // S2 = A . xg
        k_aggregate<<<agrid, 256>>>((const float4*)pT, (uint2*)pSh, (uint2*)pSl);
        // x' = relu(S2@Wn + bn + x@Wr) ; xm_next = x'*mask ; dout block i
        k_mma<3><<<ggrid, 256, DSMEM_BYTES>>>(
            pSh, pSl, H, xch, xcl, H,
            Wtnh, Wtnl, Wtrh, Wtrl,
            bn, nullptr,
            xn, xnh, xnl, pT, pTh, pTl,
            nullptr, pM, out + (size_t)i * H);

        float* tf = xc; xc = xn; xn = tf;
        bf16* th = xch; xch = xnh; xnh = th;
        bf16* tl = xcl; xcl = xnl; xnl = tl;
    }

    long long tail = (long long)out_size - (long long)N_NODES * (NLAYERS * H);
    if (tail > 0) {
        k_tail<<<(int)((tail + 255) / 256), 256>>>(out + (size_t)N_NODES * (NLAYERS * H), (int)tail);
    }
}

// round 5
// speedup vs baseline: 2.1140x; 1.2090x over previous
#include <cuda_runtime.h>
#include <cuda_fp16.h>
#include <math.h>
#include <stdint.h>

#define N_NODES 50000
#define N_EDGES 800000
#define H 256
#define F_IN 1280
#define NLAYERS 4

typedef __half h16;

// ---------------- scratch (device globals; no allocation) ----------------
__device__ __align__(256) float g_X0[N_NODES * H];
__device__ __align__(256) float g_X1[N_NODES * H];
__device__ __align__(256) float g_T [N_NODES * H];   // xm / xg (fp32, aggregation input)
__device__ __align__(256) float g_M [N_NODES * H];   // mask
__device__ __align__(256) h16  g_X0h[N_NODES * H], g_X0l[N_NODES * H];
__device__ __align__(256) h16  g_X1h[N_NODES * H], g_X1l[N_NODES * H];
__device__ __align__(256) h16  g_Th [N_NODES * H], g_Tl [N_NODES * H];
__device__ __align__(256) h16  g_Sh [N_NODES * H], g_Sl [N_NODES * H];
__device__ __align__(256) h16  g_Hbh[N_NODES * H], g_Hbl[N_NODES * H];
__device__ __align__(256) h16  g_Eh [N_NODES * F_IN], g_El[N_NODES * F_IN];
__device__ __align__(256) h16  g_W0t[H * F_IN];                 // lin0_W transposed [n][k], fp16
__device__ __align__(256) h16  g_Wt [NLAYERS * 5 * H * H];      // per (layer,type), [n][k], fp16
__device__ int   g_deg [N_NODES];
__device__ int   g_ptr [N_NODES];
__device__ int   g_fill[N_NODES];
__device__ int   g_csr [N_EDGES];
__device__ float g_degf[N_NODES];
__device__ int   g_bsum[64];

// ---------------- helpers ----------------
__device__ __forceinline__ uint32_t smem_u32(const void* p) {
    uint32_t a;
    asm("{ .reg .u64 t; cvta.to.shared.u64 t, %1; cvt.u32.u64 %0, t; }" : "=r"(a) : "l"(p));
    return a;
}
__device__ __forceinline__ void cp16(uint32_t saddr, const void* g) {
    asm volatile("cp.async.cg.shared.global [%0], [%1], 16;" :: "r"(saddr), "l"(g));
}
__device__ __forceinline__ void cp_commit() {
    asm volatile("cp.async.commit_group;" ::: "memory");
}
template<int n>
__device__ __forceinline__ void cp_wait() {
    asm volatile("cp.async.wait_group %0;" :: "n"(n) : "memory");
}
__device__ __forceinline__ void ldm4(uint32_t a, uint32_t* r) {
    asm volatile("ldmatrix.sync.aligned.m8n8.x4.shared.b16 {%0,%1,%2,%3}, [%4];"
        : "=r"(r[0]), "=r"(r[1]), "=r"(r[2]), "=r"(r[3]) : "r"(a));
}
__device__ __forceinline__ void mma16816(float* c, const uint32_t* a, const uint32_t* b) {
    asm volatile("mma.sync.aligned.m16n8k16.row.col.f32.f16.f16.f32 "
        "{%0,%1,%2,%3}, {%4,%5,%6,%7}, {%8,%9}, {%0,%1,%2,%3};"
        : "+f"(c[0]), "+f"(c[1]), "+f"(c[2]), "+f"(c[3])
        : "r"(a[0]), "r"(a[1]), "r"(a[2]), "r"(a[3]), "r"(b[0]), "r"(b[1]));
}

__device__ __forceinline__ unsigned packh2(float a, float b) {
    __half2 t = __floats2half2_rn(a, b);
    return *(unsigned*)&t;
}
__device__ __forceinline__ uint2 packh4(float a, float b, float c, float d) {
    uint2 r; r.x = packh2(a, b); r.y = packh2(c, d); return r;
}
__device__ __forceinline__ float hlo(float a) {
    return a - __half2float(__float2half(a));
}

// ---------------- CSR build ----------------
__global__ void k_zero_deg() {
    int i = blockIdx.x * blockDim.x + threadIdx.x;
    if (i < N_NODES) g_deg[i] = 0;
}
__global__ void k_hist(const int* __restrict__ dst) {
    int e = blockIdx.x * blockDim.x + threadIdx.x;
    if (e < N_EDGES) atomicAdd(&g_deg[dst[e]], 1);
}
__global__ void k_scan_block() {
    __shared__ int sh[1024];
    int i = blockIdx.x * 1024 + threadIdx.x;
    int v = (i < N_NODES) ? g_deg[i] : 0;
    sh[threadIdx.x] = v;
    __syncthreads();
    for (int off = 1; off < 1024; off <<= 1) {
        int t = (threadIdx.x >= off) ? sh[threadIdx.x - off] : 0;
        __syncthreads();
        sh[threadIdx.x] += t;
        __syncthreads();
    }
    if (i < N_NODES) g_ptr[i] = sh[threadIdx.x] - v;
    if (threadIdx.x == 1023) g_bsum[blockIdx.x] = sh[1023];
}
__global__ void k_scan_sums(int nb) {
    if (threadIdx.x == 0 && blockIdx.x == 0) {
        int run = 0;
        for (int b = 0; b < nb; b++) { int t = g_bsum[b]; g_bsum[b] = run; run += t; }
    }
}
__global__ void k_finalize() {
    int i = blockIdx.x * 1024 + threadIdx.x;
    if (i < N_NODES) {
        int p = g_ptr[i] + g_bsum[blockIdx.x];
        g_ptr[i]  = p;
        g_fill[i] = p;
        g_degf[i] = (float)g_deg[i];
    }
}
__global__ void k_fill_csr(const int* __restrict__ src, const int* __restrict__ dst) {
    int e = blockIdx.x * blockDim.x + threadIdx.x;
    if (e < N_EDGES) {
        int p = atomicAdd(&g_fill[dst[e]], 1);
        g_csr[p] = src[e];
    }
}

// ---------------- splits ----------------
__global__ void k_split(const float4* __restrict__ src, uint2* __restrict__ hi,
                        uint2* __restrict__ lo, int n4) {
    int i = blockIdx.x * blockDim.x + threadIdx.x;
    if (i < n4) {
        float4 v = __ldg(&src[i]);
        hi[i] = packh4(v.x, v.y, v.z, v.w);
        lo[i] = packh4(hlo(v.x), hlo(v.y), hlo(v.z), hlo(v.w));
    }
}
__global__ void k_splitT0(const float* __restrict__ W) {
    int i = blockIdx.x * blockDim.x + threadIdx.x;
    if (i < F_IN * H) {
        int k = i >> 8, n = i & 255;
        g_W0t[n * F_IN + k] = __float2half(__ldg(&W[i]));
    }
}
__global__ void k_splitW(const float* __restrict__ W1, const float* __restrict__ W2,
                         const float* __restrict__ W3, const float* __restrict__ Wn,
                         const float* __restrict__ Wr) {
    int i = blockIdx.x * blockDim.x + threadIdx.x;
    const int per_type = NLAYERS * H * H;
    if (i < 5 * per_type) {
        int t = i / per_type;
        int r = i - t * per_type;
        int layer = r >> 16;
        int idx = r & 65535;
        int k = idx >> 8, n = idx & 255;
        const float* src = (t == 0) ? W1 : (t == 1) ? W2 : (t == 2) ? W3 : (t == 3) ? Wn : Wr;
        size_t d = (size_t)(layer * 5 + t) * 65536 + n * 256 + k;
        g_Wt[d] = __float2half(__ldg(&src[r]));
    }
}

// ---------------- CSR gather-aggregate -> fp16 hi/lo ----------------
__global__ void k_aggregate(const float4* __restrict__ Xin,
                            uint2* __restrict__ Sh, uint2* __restrict__ Sl) {
    int node = blockIdx.x * 4 + (threadIdx.x >> 6);
    int lane = threadIdx.x & 63;
    if (node >= N_NODES) return;
    int s = g_ptr[node];
    int d = g_deg[node];
    float4 acc = make_float4(0.f, 0.f, 0.f, 0.f);
    for (int e = s; e < s + d; e++) {
        int u = __ldg(&g_csr[e]);
        float4 v = __ldg(&Xin[(size_t)u * 64 + lane]);
        acc.x += v.x; acc.y += v.y; acc.z += v.z; acc.w += v.w;
    }
    size_t o = (size_t)node * 64 + lane;
    Sh[o] = packh4(acc.x, acc.y, acc.z, acc.w);
    Sl[o] = packh4(hlo(acc.x), hlo(acc.y), hlo(acc.z), hlo(acc.w));
}

// ---------------- mma.sync GEMM: D[128 x 128] per CTA, fp16 2-term split ----------------
// BK=32; smem per matrix: 128 rows x 40 halves (32 + 8 pad) = 10240 B; Ah, Al, B
#define ROWB 80             // 40 halves * 2B
#define OFF_AH 0
#define OFF_AL 10240
#define OFF_B  20480
#define STAGE_BYTES 30720
#define DSMEM_BYTES (2 * STAGE_BYTES + 1024)

struct Tiles {
    const h16 *A0h, *A0l, *A1h, *A1l;
    const h16 *B0, *B1;
    int K0, K1;
};

__device__ __forceinline__ void load_stage_async(uint32_t st, int tid, int m0, int n0,
                                                 int kt, const Tiles& t) {
    const h16 *Ah, *Al, *B; int K, kl;
    if (kt < t.K0) { Ah = t.A0h; Al = t.A0l; B = t.B0; K = t.K0; kl = kt; }
    else           { Ah = t.A1h; Al = t.A1l; B = t.B1; K = t.K1; kl = kt - t.K0; }
    #pragma unroll
    for (int l = 0; l < 2; l++) {
        int f = tid + l * 256;
        int r = f >> 2, q = f & 3;
        int m = m0 + r; if (m >= N_NODES) m = N_NODES - 1;
        size_t g = (size_t)m * K + kl + q * 8;
        uint32_t s = st + r * ROWB + q * 16;
        cp16(s + OFF_AH, Ah + g);
        cp16(s + OFF_AL, Al + g);
    }
    #pragma unroll
    for (int l = 0; l < 2; l++) {
        int f = tid + l * 256;
        int r = f >> 2, q = f & 3;
        size_t g = (size_t)(n0 + r) * K + kl + q * 8;
        cp16(st + OFF_B + r * ROWB + q * 16, B + g);
    }
}

// MODE 0 (lin0): v = acc+b       -> OA,OAh,OAl and OB,OBh,OBl (duplicate)
// MODE 1 (h)   : v = relu(acc+b1+deg*b2) -> OAh,OAl
// MODE 2 (mask): mk=sigmoid(acc+b3) -> OA=mask; OB = mk*Xin (xg, fp32 only)
// MODE 3 (x')  : v = relu(acc+bn) -> OA,OAh,OAl; OB=v*Mask,OBh,OBl; Dout
template<int MODE>
__global__ void __launch_bounds__(256, 2) k_mma(
    const h16* A0h, const h16* A0l, int K0,
    const h16* A1h, const h16* A1l, int K1,
    const h16* B0, const h16* B1,
    const float* __restrict__ bias, const float* __restrict__ bias2,
    float* __restrict__ OA, h16* __restrict__ OAh, h16* __restrict__ OAl,
    float* __restrict__ OB, h16* __restrict__ OBh, h16* __restrict__ OBl,
    const float* __restrict__ Xin, const float* __restrict__ Mask,
    float* __restrict__ Dout)
{
    extern __shared__ char dsm_raw[];
    char* sbase = (char*)(((uintptr_t)dsm_raw + 1023) & ~(uintptr_t)1023);
    const uint32_t sb32 = smem_u32(sbase);

    const int tid = threadIdx.x;
    const int wid = tid >> 5;
    const int lane = tid & 31;
    const int wm = wid & 3;     // 4 m-groups of 32 rows
    const int wn = wid >> 2;    // 2 n-groups of 64 cols
    const int m0 = blockIdx.x * 128;
    const int n0 = blockIdx.y * 128;

    Tiles t; t.A0h = A0h; t.A0l = A0l; t.A1h = A1h; t.A1l = A1l;
    t.B0 = B0; t.B1 = B1; t.K0 = K0; t.K1 = K1;

    float c[2][8][4];
    #pragma unroll
    for (int i = 0; i < 2; i++)
        #pragma unroll
        for (int j = 0; j < 8; j++)
            #pragma unroll
            for (int q = 0; q < 4; q++) c[i][j][q] = 0.f;

    const int nIter = (K0 + K1) >> 5;

    load_stage_async(sb32, tid, m0, n0, 0, t);
    cp_commit();

    const uint32_t aAddrBase = (wm * 32 + (lane & 15)) * ROWB + (lane >> 4) * 16;
    const uint32_t bAddrBase = (wn * 64 + (lane & 7) + ((lane >> 4) & 1) * 8) * ROWB
                             + ((lane >> 3) & 1) * 16;

    for (int it = 0; it < nIter; ++it) {
        const uint32_t stu = sb32 + (it & 1) * STAGE_BYTES;
        if (it + 1 < nIter) {
            load_stage_async(sb32 + ((it + 1) & 1) * STAGE_BYTES, tid, m0, n0, (it + 1) << 5, t);
            cp_commit();
            cp_wait<1>();
        } else {
            cp_wait<0>();
        }
        __syncthreads();

        #pragma unroll
        for (int ks = 0; ks < 2; ks++) {
            const uint32_t kb = ks * 32;   // 16 halves * 2B
            uint32_t ah[2][4], al[2][4], bfr[4][4];
            #pragma unroll
            for (int mt = 0; mt < 2; mt++) {
                ldm4(stu + OFF_AH + aAddrBase + mt * (16 * ROWB) + kb, ah[mt]);
                ldm4(stu + OFF_AL + aAddrBase + mt * (16 * ROWB) + kb, al[mt]);
            }
            #pragma unroll
            for (int nt = 0; nt < 4; nt++)
                ldm4(stu + OFF_B + bAddrBase + nt * (16 * ROWB) + kb, bfr[nt]);
            #pragma unroll
            for (int mt = 0; mt < 2; mt++)
                #pragma unroll
                for (int nt = 0; nt < 4; nt++) {
                    mma16816(c[mt][nt * 2 + 0], ah[mt], &bfr[nt][0]);
                    mma16816(c[mt][nt * 2 + 1], ah[mt], &bfr[nt][2]);
                    mma16816(c[mt][nt * 2 + 0], al[mt], &bfr[nt][0]);
                    mma16816(c[mt][nt * 2 + 1], al[mt], &bfr[nt][2]);
                }
        }
        __syncthreads();
    }

    // ---- C regs -> smem staging, two 64-col halves (smem = 128 x 68 floats) ----
    float* stg = (float*)sbase;
    #pragma unroll
    for (int hh = 0; hh < 2; hh++) {
        if (wn == hh) {
            #pragma unroll
            for (int mt = 0; mt < 2; mt++) {
                #pragma unroll
                for (int nt = 0; nt < 8; nt++) {
                    int r0 = wm * 32 + mt * 16 + (lane >> 2);
                    int col = nt * 8 + (lane & 3) * 2;
                    *(float2*)&stg[r0 * 68 + col]       = make_float2(c[mt][nt][0], c[mt][nt][1]);
                    *(float2*)&stg[(r0 + 8) * 68 + col] = make_float2(c[mt][nt][2], c[mt][nt][3]);
                }
            }
        }
        __syncthreads();

        #pragma unroll
        for (int p = 0; p < 8; p++) {
            int f = tid + p * 256;
            int row = f >> 4;
            int c4 = f & 15;
            int m = m0 + row;
            if (m < N_NODES) {
                int col = c4 * 4;
                int gcol = n0 + hh * 64 + col;
                float4 v = *(float4*)&stg[row * 68 + col];
                float4 b4 = __ldg((const float4*)(bias + gcol));
                float v0 = v.x + b4.x, v1 = v.y + b4.y, v2 = v.z + b4.z, v3 = v.w + b4.w;
                size_t off = (size_t)m * H + gcol;
                if (MODE == 0) {
                    float4 vv = make_float4(v0, v1, v2, v3);
                    *(float4*)(OA + off) = vv;
                    *(float4*)(OB + off) = vv;
                    uint2 hhh = packh4(v0, v1, v2, v3);
                    uint2 lll = packh4(hlo(v0), hlo(v1), hlo(v2), hlo(v3));
                    *(uint2*)(OAh + off) = hhh; *(uint2*)(OAl + off) = lll;
                    *(uint2*)(OBh + off) = hhh; *(uint2*)(OBl + off) = lll;
                }
                if (MODE == 1) {
                    float dv = g_degf[m];
                    float4 b2v = __ldg((const float4*)(bias2 + gcol));
                    v0 = fmaxf(v0 + dv * b2v.x, 0.f);
                    v1 = fmaxf(v1 + dv * b2v.y, 0.f);
                    v2 = fmaxf(v2 + dv * b2v.z, 0.f);
                    v3 = fmaxf(v3 + dv * b2v.w, 0.f);
                    *(uint2*)(OAh + off) = packh4(v0, v1, v2, v3);
                    *(uint2*)(OAl + off) = packh4(hlo(v0), hlo(v1), hlo(v2), hlo(v3));
                }
                if (MODE == 2) {
                    v0 = 1.f / (1.f + expf(-v0));
                    v1 = 1.f / (1.f + expf(-v1));
                    v2 = 1.f / (1.f + expf(-v2));
                    v3 = 1.f / (1.f + expf(-v3));
                    *(float4*)(OA + off) = make_float4(v0, v1, v2, v3);
                    float4 xv = __ldg((const float4*)(Xin + off));
                    *(float4*)(OB + off) = make_float4(v0 * xv.x, v1 * xv.y, v2 * xv.z, v3 * xv.w);
                }
                if (MODE == 3) {
                    v0 = fmaxf(v0, 0.f); v1 = fmaxf(v1, 0.f);
                    v2 = fmaxf(v2, 0.f); v3 = fmaxf(v3, 0.f);
                    *(float4*)(OA + off) = make_float4(v0, v1, v2, v3);
                    *(uint2*)(OAh + off) = packh4(v0, v1, v2, v3);
                    *(uint2*)(OAl + off) = packh4(hlo(v0), hlo(v1), hlo(v2), hlo(v3));
                    float4 mv = __ldg((const float4*)(Mask + off));
                    float t0 = v0 * mv.x, t1 = v1 * mv.y, t2 = v2 * mv.z, t3 = v3 * mv.w;
                    *(float4*)(OB + off) = make_float4(t0, t1, t2, t3);
                    *(uint2*)(OBh + off) = packh4(t0, t1, t2, t3);
                    *(uint2*)(OBl + off) = packh4(hlo(t0), hlo(t1), hlo(t2), hlo(t3));
                    *(float4*)(Dout + (size_t)m * (NLAYERS * H) + gcol) = make_float4(v0, v1, v2, v3);
                }
            }
        }
        __syncthreads();
    }
}

__global__ void k_tail(float* p, int n) {
    int i = blockIdx.x * blockDim.x + threadIdx.x;
    if (i < n) p[i] = 1.0f;
}

// ---------------- launch ----------------
extern "C" void kernel_launch(void* const* d_in, const int* in_sizes, int n_in,
                              void* d_out, int out_size)
{
    (void)in_sizes; (void)n_in;
    const int*   edge   = (const int*)  d_in[1];
    const float* esm    = (const float*)d_in[2];
    const float* lin0_W = (const float*)d_in[4];
    const float* lin0_b = (const float*)d_in[5];
    const float* wc_W1  = (const float*)d_in[6];
    const float* wc_b1  = (const float*)d_in[7];
    const float* wc_W2  = (const float*)d_in[8];
    const float* wc_b2  = (const float*)d_in[9];
    const float* wc_W3  = (const float*)d_in[10];
    const float* wc_b3  = (const float*)d_in[11];
    const float* sc_Wn  = (const float*)d_in[12];
    const float* sc_bn  = (const float*)d_in[13];
    const float* sc_Wr  = (const float*)d_in[14];
    float* out = (float*)d_out;

    const int* src = edge;
    const int* dst = edge + N_EDGES;

    cudaFuncSetAttribute(k_mma<0>, cudaFuncAttributeMaxDynamicSharedMemorySize, DSMEM_BYTES);
    cudaFuncSetAttribute(k_mma<1>, cudaFuncAttributeMaxDynamicSharedMemorySize, DSMEM_BYTES);
    cudaFuncSetAttribute(k_mma<2>, cudaFuncAttributeMaxDynamicSharedMemorySize, DSMEM_BYTES);
    cudaFuncSetAttribute(k_mma<3>, cudaFuncAttributeMaxDynamicSharedMemorySize, DSMEM_BYTES);

    float *pX0, *pX1, *pM, *pT;
    h16 *pX0h, *pX0l, *pX1h, *pX1l, *pTh, *pTl, *pSh, *pSl, *pHbh, *pHbl;
    h16 *pEh, *pEl, *pW0, *pWt;
    cudaGetSymbolAddress((void**)&pX0, g_X0);
    cudaGetSymbolAddress((void**)&pX1, g_X1);
    cudaGetSymbolAddress((void**)&pM,  g_M);
    cudaGetSymbolAddress((void**)&pT,  g_T);
    cudaGetSymbolAddress((void**)&pX0h, g_X0h); cudaGetSymbolAddress((void**)&pX0l, g_X0l);
    cudaGetSymbolAddress((void**)&pX1h, g_X1h); cudaGetSymbolAddress((void**)&pX1l, g_X1l);
    cudaGetSymbolAddress((void**)&pTh, g_Th);   cudaGetSymbolAddress((void**)&pTl, g_Tl);
    cudaGetSymbolAddress((void**)&pSh, g_Sh);   cudaGetSymbolAddress((void**)&pSl, g_Sl);
    cudaGetSymbolAddress((void**)&pHbh, g_Hbh); cudaGetSymbolAddress((void**)&pHbl, g_Hbl);
    cudaGetSymbolAddress((void**)&pEh, g_Eh);   cudaGetSymbolAddress((void**)&pEl, g_El);
    cudaGetSymbolAddress((void**)&pW0, g_W0t);
    cudaGetSymbolAddress((void**)&pWt, g_Wt);

    // CSR build
    k_zero_deg<<<(N_NODES + 255) / 256, 256>>>();
    k_hist    <<<(N_EDGES + 255) / 256, 256>>>(dst);
    int nblk = (N_NODES + 1023) / 1024;
    k_scan_block<<<nblk, 1024>>>();
    k_scan_sums <<<1, 32>>>(nblk);
    k_finalize  <<<nblk, 1024>>>();
    k_fill_csr  <<<(N_EDGES + 255) / 256, 256>>>(src, dst);

    // input / weight splits
    k_split<<<(N_NODES * F_IN / 4 + 255) / 256, 256>>>((const float4*)esm, (uint2*)pEh, (uint2*)pEl, N_NODES * F_IN / 4);
    k_splitT0<<<(F_IN * H + 255) / 256, 256>>>(lin0_W);
    k_splitW<<<(5 * NLAYERS * H * H + 255) / 256, 256>>>(wc_W1, wc_W2, wc_W3, sc_Wn, sc_Wr);

    dim3 ggrid((N_NODES + 127) / 128, 2);   // 391 x 2
    dim3 agrid((N_NODES + 3) / 4);          // 12500

    // lin0: x = esm @ W0 + b0 ; T = x
    k_mma<0><<<ggrid, 256, DSMEM_BYTES>>>(
        pEh, pEl, F_IN, pEh, pEl, 0,
        pW0, pW0,
        lin0_b, nullptr,
        pX0, pX0h, pX0l, pT, pTh, pTl,
        nullptr, nullptr, nullptr);

    float* xc = pX0;  h16* xch = pX0h; h16* xcl = pX0l;
    float* xn = pX1;  h16* xnh = pX1h; h16* xnl = pX1l;
    for (int i = 0; i < NLAYERS; i++) {
        h16* Wt1 = pWt + (size_t)(i * 5 + 0) * 65536;
        h16* Wt2 = pWt + (size_t)(i * 5 + 1) * 65536;
        h16* Wt3 = pWt + (size_t)(i * 5 + 2) * 65536;
        h16* Wtn = pWt + (size_t)(i * 5 + 3) * 65536;
        h16* Wtr = pWt + (size_t)(i * 5 + 4) * 65536;
        const float* b1 = wc_b1 + (size_t)i * H;
        const float* b2 = wc_b2 + (size_t)i * H;
        const float* b3 = wc_b3 + (size_t)i * H;
        const float* bn = sc_bn + (size_t)i * H;

        // S = A . xm
        k_aggregate<<<agrid, 256>>>((const float4*)pT, (uint2*)pSh, (uint2*)pSl);
        // h = relu(S@W2 + deg*b2 + xm@W1 + b1)
        k_mma<1><<<ggrid, 256, DSMEM_BYTES>>>(
            pSh, pSl, H, pTh, pTl, H,
            Wt2, Wt1,
            b1, b2,
            nullptr, pHbh, pHbl, nullptr, nullptr, nullptr,
            nullptr, nullptr, nullptr);
        // mask = sigmoid(h@W3 + b3) ; xg = x * mask
        k_mma<2><<<ggrid, 256, DSMEM_BYTES>>>(
            pHbh, pHbl, H, pHbh, pHbl, 0,
            Wt3, Wt3,
            b3, nullptr,
            pM, nullptr, nullptr, pT, nullptr, nullptr,
            xc, nullptr, nullptr);
        // S2 = A . xg
        k_aggregate<<<agrid, 256>>>((const float4*)pT, (uint2*)pSh, (uint2*)pSl);
        // x' = relu(S2@Wn + bn + x@Wr) ; xm_next = x'*mask ; dout block i
        k_mma<3><<<ggrid, 256, DSMEM_BYTES>>>(
            pSh, pSl, H, xch, xcl, H,
            Wtn, Wtr,
            bn, nullptr,
            xn, xnh, xnl, pT, pTh, pTl,
            nullptr, pM, out + (size_t)i * H);

        float* tf = xc; xc = xn; xn = tf;
        h16* th = xch; xch = xnh; xnh = th;
        h16* tl = xcl; xcl = xnl; xnl = tl;
    }

    long long tail = (long long)out_size - (long long)N_NODES * (NLAYERS * H);
    if (tail > 0) {
        k_tail<<<(int)((tail + 255) / 256), 256>>>(out + (size_t)N_NODES * (NLAYERS * H), (int)tail);
    }
}

// round 6
// speedup vs baseline: 2.4008x; 1.1356x over previous
#include <cuda_runtime.h>
#include <cuda_fp16.h>
#include <math.h>
#include <stdint.h>

#define N_NODES 50000
#define N_EDGES 800000
#define H 256
#define F_IN 1280
#define NLAYERS 4

typedef __half h16;

// ---------------- scratch (device globals; no allocation) ----------------
__device__ __align__(256) float g_X0[N_NODES * H];
__device__ __align__(256) float g_X1[N_NODES * H];
__device__ __align__(256) float g_T [N_NODES * H];   // xm / xg (fp32, aggregation input)
__device__ __align__(256) float g_M [N_NODES * H];   // mask
__device__ __align__(256) h16  g_X0h[N_NODES * H], g_X0l[N_NODES * H];
__device__ __align__(256) h16  g_X1h[N_NODES * H], g_X1l[N_NODES * H];
__device__ __align__(256) h16  g_Th [N_NODES * H];
__device__ __align__(256) h16  g_Sh [N_NODES * H], g_Sl [N_NODES * H];
__device__ __align__(256) h16  g_Hbh[N_NODES * H];
__device__ __align__(256) h16  g_Eh [N_NODES * F_IN], g_El[N_NODES * F_IN];
__device__ __align__(256) h16  g_W0t[H * F_IN];                 // lin0_W transposed [n][k], fp16
__device__ __align__(256) h16  g_Wt [NLAYERS * 5 * H * H];      // per (layer,type), [n][k], fp16
__device__ int   g_deg [N_NODES];
__device__ int   g_ptr [N_NODES];
__device__ int   g_fill[N_NODES];
__device__ int   g_csr [N_EDGES];
__device__ float g_degf[N_NODES];
__device__ int   g_bsum[64];

// ---------------- helpers ----------------
__device__ __forceinline__ uint32_t smem_u32(const void* p) {
    uint32_t a;
    asm("{ .reg .u64 t; cvta.to.shared.u64 t, %1; cvt.u32.u64 %0, t; }" : "=r"(a) : "l"(p));
    return a;
}
__device__ __forceinline__ void cp16(uint32_t saddr, const void* g) {
    asm volatile("cp.async.cg.shared.global [%0], [%1], 16;" :: "r"(saddr), "l"(g));
}
__device__ __forceinline__ void cp_commit() {
    asm volatile("cp.async.commit_group;" ::: "memory");
}
template<int n>
__device__ __forceinline__ void cp_wait() {
    asm volatile("cp.async.wait_group %0;" :: "n"(n) : "memory");
}
__device__ __forceinline__ void ldm4(uint32_t a, uint32_t* r) {
    asm volatile("ldmatrix.sync.aligned.m8n8.x4.shared.b16 {%0,%1,%2,%3}, [%4];"
        : "=r"(r[0]), "=r"(r[1]), "=r"(r[2]), "=r"(r[3]) : "r"(a));
}
__device__ __forceinline__ void mma16816(float* c, const uint32_t* a, const uint32_t* b) {
    asm volatile("mma.sync.aligned.m16n8k16.row.col.f32.f16.f16.f32 "
        "{%0,%1,%2,%3}, {%4,%5,%6,%7}, {%8,%9}, {%0,%1,%2,%3};"
        : "+f"(c[0]), "+f"(c[1]), "+f"(c[2]), "+f"(c[3])
        : "r"(a[0]), "r"(a[1]), "r"(a[2]), "r"(a[3]), "r"(b[0]), "r"(b[1]));
}

__device__ __forceinline__ unsigned packh2(float a, float b) {
    __half2 t = __floats2half2_rn(a, b);
    return *(unsigned*)&t;
}
__device__ __forceinline__ uint2 packh4(float a, float b, float c, float d) {
    uint2 r; r.x = packh2(a, b); r.y = packh2(c, d); return r;
}
__device__ __forceinline__ float hlo(float a) {
    return a - __half2float(__float2half(a));
}

// ---------------- CSR build ----------------
__global__ void k_zero_deg() {
    int i = blockIdx.x * blockDim.x + threadIdx.x;
    if (i < N_NODES) g_deg[i] = 0;
}
__global__ void k_scan_block() {
    __shared__ int sh[1024];
    int i = blockIdx.x * 1024 + threadIdx.x;
    int v = (i < N_NODES) ? g_deg[i] : 0;
    sh[threadIdx.x] = v;
    __syncthreads();
    for (int off = 1; off < 1024; off <<= 1) {
        int t = (threadIdx.x >= off) ? sh[threadIdx.x - off] : 0;
        __syncthreads();
        sh[threadIdx.x] += t;
        __syncthreads();
    }
    if (i < N_NODES) g_ptr[i] = sh[threadIdx.x] - v;
    if (threadIdx.x == 1023) g_bsum[blockIdx.x] = sh[1023];
}
__global__ void k_scan_sums(int nb) {
    if (threadIdx.x == 0 && blockIdx.x == 0) {
        int run = 0;
        for (int b = 0; b < nb; b++) { int t = g_bsum[b]; g_bsum[b] = run; run += t; }
    }
}
__global__ void k_finalize() {
    int i = blockIdx.x * 1024 + threadIdx.x;
    if (i < N_NODES) {
        int p = g_ptr[i] + g_bsum[blockIdx.x];
        g_ptr[i]  = p;
        g_fill[i] = p;
        g_degf[i] = (float)g_deg[i];
    }
}

// ---------------- fused: esm split + degree histogram ----------------
#define NB_SPLIT (N_NODES * F_IN / 4 / 256)    // 62500
#define NB_HIST  (N_EDGES / 256)               // 3125
__global__ void k_split_hist(const float4* __restrict__ src, uint2* __restrict__ hi,
                             uint2* __restrict__ lo, const int* __restrict__ dst) {
    int b = blockIdx.x;
    if (b < NB_SPLIT) {
        int i = b * 256 + threadIdx.x;
        float4 v = __ldg(&src[i]);
        hi[i] = packh4(v.x, v.y, v.z, v.w);
        lo[i] = packh4(hlo(v.x), hlo(v.y), hlo(v.z), hlo(v.w));
    } else {
        int e = (b - NB_SPLIT) * 256 + threadIdx.x;
        atomicAdd(&g_deg[dst[e]], 1);
    }
}

// ---------------- fused: weight split + CSR fill ----------------
#define NB_W (5 * NLAYERS * H * H / 256)       // 5120
__global__ void k_splitW_fill(const float* __restrict__ W1, const float* __restrict__ W2,
                              const float* __restrict__ W3, const float* __restrict__ Wn,
                              const float* __restrict__ Wr,
                              const int* __restrict__ src_e, const int* __restrict__ dst_e) {
    int b = blockIdx.x;
    if (b < NB_W) {
        int i = b * 256 + threadIdx.x;
        const int per_type = NLAYERS * H * H;
        int t = i / per_type;
        int r = i - t * per_type;
        int layer = r >> 16;
        int idx = r & 65535;
        int k = idx >> 8, n = idx & 255;
        const float* src = (t == 0) ? W1 : (t == 1) ? W2 : (t == 2) ? W3 : (t == 3) ? Wn : Wr;
        size_t d = (size_t)(layer * 5 + t) * 65536 + n * 256 + k;
        g_Wt[d] = __float2half(__ldg(&src[r]));
    } else {
        int e = (b - NB_W) * 256 + threadIdx.x;
        int p = atomicAdd(&g_fill[dst_e[e]], 1);
        g_csr[p] = src_e[e];
    }
}

__global__ void k_splitT0(const float* __restrict__ W) {
    int i = blockIdx.x * blockDim.x + threadIdx.x;
    if (i < F_IN * H) {
        int k = i >> 8, n = i & 255;
        g_W0t[n * F_IN + k] = __float2half(__ldg(&W[i]));
    }
}

// ---------------- CSR gather-aggregate -> fp16 hi/lo (MLP-4 unrolled) ----------------
__global__ void k_aggregate(const float4* __restrict__ Xin,
                            uint2* __restrict__ Sh, uint2* __restrict__ Sl) {
    int node = blockIdx.x * 4 + (threadIdx.x >> 6);
    int lane = threadIdx.x & 63;
    if (node >= N_NODES) return;
    int s = g_ptr[node];
    int d = g_deg[node];
    int end = s + d;
    float4 acc = make_float4(0.f, 0.f, 0.f, 0.f);
    int e = s;
    for (; e + 4 <= end; e += 4) {
        int u0 = __ldg(&g_csr[e + 0]);
        int u1 = __ldg(&g_csr[e + 1]);
        int u2 = __ldg(&g_csr[e + 2]);
        int u3 = __ldg(&g_csr[e + 3]);
        float4 v0 = __ldg(&Xin[(size_t)u0 * 64 + lane]);
        float4 v1 = __ldg(&Xin[(size_t)u1 * 64 + lane]);
        float4 v2 = __ldg(&Xin[(size_t)u2 * 64 + lane]);
        float4 v3 = __ldg(&Xin[(size_t)u3 * 64 + lane]);
        acc.x += (v0.x + v1.x) + (v2.x + v3.x);
        acc.y += (v0.y + v1.y) + (v2.y + v3.y);
        acc.z += (v0.z + v1.z) + (v2.z + v3.z);
        acc.w += (v0.w + v1.w) + (v2.w + v3.w);
    }
    for (; e < end; e++) {
        int u = __ldg(&g_csr[e]);
        float4 v = __ldg(&Xin[(size_t)u * 64 + lane]);
        acc.x += v.x; acc.y += v.y; acc.z += v.z; acc.w += v.w;
    }
    size_t o = (size_t)node * 64 + lane;
    Sh[o] = packh4(acc.x, acc.y, acc.z, acc.w);
    Sl[o] = packh4(hlo(acc.x), hlo(acc.y), hlo(acc.z), hlo(acc.w));
}

// ---------------- mma.sync GEMM: D[128 x 128] per CTA, fp16 1- or 2-term ----------------
#define ROWB 80             // 40 halves * 2B
#define OFF_AH 0
#define OFF_AL 10240
#define OFF_B  20480
#define STAGE_BYTES 30720
#define DSMEM_BYTES (2 * STAGE_BYTES + 1024)

struct Tiles {
    const h16 *A0h, *A0l, *A1h, *A1l;
    const h16 *B0, *B1;
    int K0, K1;
};

template<bool TWO>
__device__ __forceinline__ void load_stage_async(uint32_t st, int tid, int m0, int n0,
                                                 int kt, const Tiles& t) {
    const h16 *Ah, *Al, *B; int K, kl;
    if (kt < t.K0) { Ah = t.A0h; Al = t.A0l; B = t.B0; K = t.K0; kl = kt; }
    else           { Ah = t.A1h; Al = t.A1l; B = t.B1; K = t.K1; kl = kt - t.K0; }
    #pragma unroll
    for (int l = 0; l < 2; l++) {
        int f = tid + l * 256;
        int r = f >> 2, q = f & 3;
        int m = m0 + r; if (m >= N_NODES) m = N_NODES - 1;
        size_t g = (size_t)m * K + kl + q * 8;
        uint32_t s = st + r * ROWB + q * 16;
        cp16(s + OFF_AH, Ah + g);
        if (TWO) cp16(s + OFF_AL, Al + g);
    }
    #pragma unroll
    for (int l = 0; l < 2; l++) {
        int f = tid + l * 256;
        int r = f >> 2, q = f & 3;
        size_t g = (size_t)(n0 + r) * K + kl + q * 8;
        cp16(st + OFF_B + r * ROWB + q * 16, B + g);
    }
}

// MODE 0 (lin0): v = acc+b -> OA,OAh,OAl (+OB set if non-null)
// MODE 1 (h)   : v = relu(acc+b1+deg*b2) -> OAh (+OAl if non-null)
// MODE 2 (mask): mk=sigmoid(acc+b3) -> OA=mask; OB = mk*Xin (fp32)
// MODE 3 (x')  : v = relu(acc+bn) -> OA,OAh,OAl; OB=v*Mask fp32,OBh (+OBl if non-null); Dout
template<int MODE, bool TWO>
__global__ void __launch_bounds__(256, 2) k_mma(
    const h16* A0h, const h16* A0l, int K0,
    const h16* A1h, const h16* A1l, int K1,
    const h16* B0, const h16* B1,
    const float* __restrict__ bias, const float* __restrict__ bias2,
    float* __restrict__ OA, h16* __restrict__ OAh, h16* __restrict__ OAl,
    float* __restrict__ OB, h16* __restrict__ OBh, h16* __restrict__ OBl,
    const float* __restrict__ Xin, const float* __restrict__ Mask,
    float* __restrict__ Dout)
{
    extern __shared__ char dsm_raw[];
    char* sbase = (char*)(((uintptr_t)dsm_raw + 1023) & ~(uintptr_t)1023);
    const uint32_t sb32 = smem_u32(sbase);

    const int tid = threadIdx.x;
    const int wid = tid >> 5;
    const int lane = tid & 31;
    const int wm = wid & 3;
    const int wn = wid >> 2;
    const int m0 = blockIdx.x * 128;
    const int n0 = blockIdx.y * 128;

    Tiles t; t.A0h = A0h; t.A0l = A0l; t.A1h = A1h; t.A1l = A1l;
    t.B0 = B0; t.B1 = B1; t.K0 = K0; t.K1 = K1;

    float c[2][8][4];
    #pragma unroll
    for (int i = 0; i < 2; i++)
        #pragma unroll
        for (int j = 0; j < 8; j++)
            #pragma unroll
            for (int q = 0; q < 4; q++) c[i][j][q] = 0.f;

    const int nIter = (K0 + K1) >> 5;

    load_stage_async<TWO>(sb32, tid, m0, n0, 0, t);
    cp_commit();

    const uint32_t aAddrBase = (wm * 32 + (lane & 15)) * ROWB + (lane >> 4) * 16;
    const uint32_t bAddrBase = (wn * 64 + (lane & 7) + ((lane >> 4) & 1) * 8) * ROWB
                             + ((lane >> 3) & 1) * 16;

    for (int it = 0; it < nIter; ++it) {
        const uint32_t stu = sb32 + (it & 1) * STAGE_BYTES;
        if (it + 1 < nIter) {
            load_stage_async<TWO>(sb32 + ((it + 1) & 1) * STAGE_BYTES, tid, m0, n0, (it + 1) << 5, t);
            cp_commit();
            cp_wait<1>();
        } else {
            cp_wait<0>();
        }
        __syncthreads();

        #pragma unroll
        for (int ks = 0; ks < 2; ks++) {
            const uint32_t kb = ks * 32;
            uint32_t ah[2][4], bfr[4][4];
            #pragma unroll
            for (int mt = 0; mt < 2; mt++)
                ldm4(stu + OFF_AH + aAddrBase + mt * (16 * ROWB) + kb, ah[mt]);
            #pragma unroll
            for (int nt = 0; nt < 4; nt++)
                ldm4(stu + OFF_B + bAddrBase + nt * (16 * ROWB) + kb, bfr[nt]);
            #pragma unroll
            for (int mt = 0; mt < 2; mt++)
                #pragma unroll
                for (int nt = 0; nt < 4; nt++) {
                    mma16816(c[mt][nt * 2 + 0], ah[mt], &bfr[nt][0]);
                    mma16816(c[mt][nt * 2 + 1], ah[mt], &bfr[nt][2]);
                }
            if (TWO) {
                uint32_t al[2][4];
                #pragma unroll
                for (int mt = 0; mt < 2; mt++)
                    ldm4(stu + OFF_AL + aAddrBase + mt * (16 * ROWB) + kb, al[mt]);
                #pragma unroll
                for (int mt = 0; mt < 2; mt++)
                    #pragma unroll
                    for (int nt = 0; nt < 4; nt++) {
                        mma16816(c[mt][nt * 2 + 0], al[mt], &bfr[nt][0]);
                        mma16816(c[mt][nt * 2 + 1], al[mt], &bfr[nt][2]);
                    }
            }
        }
        __syncthreads();
    }

    // ---- C regs -> smem staging, two 64-col halves (smem = 128 x 68 floats) ----
    float* stg = (float*)sbase;
    #pragma unroll
    for (int hh = 0; hh < 2; hh++) {
        if (wn == hh) {
            #pragma unroll
            for (int mt = 0; mt < 2; mt++) {
                #pragma unroll
                for (int nt = 0; nt < 8; nt++) {
                    int r0 = wm * 32 + mt * 16 + (lane >> 2);
                    int col = nt * 8 + (lane & 3) * 2;
                    *(float2*)&stg[r0 * 68 + col]       = make_float2(c[mt][nt][0], c[mt][nt][1]);
                    *(float2*)&stg[(r0 + 8) * 68 + col] = make_float2(c[mt][nt][2], c[mt][nt][3]);
                }
            }
        }
        __syncthreads();

        #pragma unroll
        for (int p = 0; p < 8; p++) {
            int f = tid + p * 256;
            int row = f >> 4;
            int c4 = f & 15;
            int m = m0 + row;
            if (m < N_NODES) {
                int col = c4 * 4;
                int gcol = n0 + hh * 64 + col;
                float4 v = *(float4*)&stg[row * 68 + col];
                float4 b4 = __ldg((const float4*)(bias + gcol));
                float v0 = v.x + b4.x, v1 = v.y + b4.y, v2 = v.z + b4.z, v3 = v.w + b4.w;
                size_t off = (size_t)m * H + gcol;
                if (MODE == 0) {
                    float4 vv = make_float4(v0, v1, v2, v3);
                    *(float4*)(OA + off) = vv;
                    if (OB) *(float4*)(OB + off) = vv;
                    uint2 hhh = packh4(v0, v1, v2, v3);
                    uint2 lll = packh4(hlo(v0), hlo(v1), hlo(v2), hlo(v3));
                    *(uint2*)(OAh + off) = hhh; *(uint2*)(OAl + off) = lll;
                    if (OBh) *(uint2*)(OBh + off) = hhh;
                    if (OBl) *(uint2*)(OBl + off) = lll;
                }
                if (MODE == 1) {
                    float dv = g_degf[m];
                    float4 b2v = __ldg((const float4*)(bias2 + gcol));
                    v0 = fmaxf(v0 + dv * b2v.x, 0.f);
                    v1 = fmaxf(v1 + dv * b2v.y, 0.f);
                    v2 = fmaxf(v2 + dv * b2v.z, 0.f);
                    v3 = fmaxf(v3 + dv * b2v.w, 0.f);
                    *(uint2*)(OAh + off) = packh4(v0, v1, v2, v3);
                    if (OAl) *(uint2*)(OAl + off) = packh4(hlo(v0), hlo(v1), hlo(v2), hlo(v3));
                }
                if (MODE == 2) {
                    v0 = 1.f / (1.f + expf(-v0));
                    v1 = 1.f / (1.f + expf(-v1));
                    v2 = 1.f / (1.f + expf(-v2));
                    v3 = 1.f / (1.f + expf(-v3));
                    *(float4*)(OA + off) = make_float4(v0, v1, v2, v3);
                    float4 xv = __ldg((const float4*)(Xin + off));
                    *(float4*)(OB + off) = make_float4(v0 * xv.x, v1 * xv.y, v2 * xv.z, v3 * xv.w);
                }
                if (MODE == 3) {
                    v0 = fmaxf(v0, 0.f); v1 = fmaxf(v1, 0.f);
                    v2 = fmaxf(v2, 0.f); v3 = fmaxf(v3, 0.f);
                    *(float4*)(OA + off) = make_float4(v0, v1, v2, v3);
                    *(uint2*)(OAh + off) = packh4(v0, v1, v2, v3);
                    *(uint2*)(OAl + off) = packh4(hlo(v0), hlo(v1), hlo(v2), hlo(v3));
                    float4 mv = __ldg((const float4*)(Mask + off));
                    float t0 = v0 * mv.x, t1 = v1 * mv.y, t2 = v2 * mv.z, t3 = v3 * mv.w;
                    *(float4*)(OB + off) = make_float4(t0, t1, t2, t3);
                    *(uint2*)(OBh + off) = packh4(t0, t1, t2, t3);
                    if (OBl) *(uint2*)(OBl + off) = packh4(hlo(t0), hlo(t1), hlo(t2), hlo(t3));
                    *(float4*)(Dout + (size_t)m * (NLAYERS * H) + gcol) = make_float4(v0, v1, v2, v3);
                }
            }
        }
        __syncthreads();
    }
}

__global__ void k_tail(float* p, int n) {
    int i = blockIdx.x * blockDim.x + threadIdx.x;
    if (i < n) p[i] = 1.0f;
}

// ---------------- launch ----------------
extern "C" void kernel_launch(void* const* d_in, const int* in_sizes, int n_in,
                              void* d_out, int out_size)
{
    (void)in_sizes; (void)n_in;
    const int*   edge   = (const int*)  d_in[1];
    const float* esm    = (const float*)d_in[2];
    const float* lin0_W = (const float*)d_in[4];
    const float* lin0_b = (const float*)d_in[5];
    const float* wc_W1  = (const float*)d_in[6];
    const float* wc_b1  = (const float*)d_in[7];
    const float* wc_W2  = (const float*)d_in[8];
    const float* wc_b2  = (const float*)d_in[9];
    const float* wc_W3  = (const float*)d_in[10];
    const float* wc_b3  = (const float*)d_in[11];
    const float* sc_Wn  = (const float*)d_in[12];
    const float* sc_bn  = (const float*)d_in[13];
    const float* sc_Wr  = (const float*)d_in[14];
    float* out = (float*)d_out;

    const int* src = edge;
    const int* dst = edge + N_EDGES;

    cudaFuncSetAttribute(k_mma<0,true>,  cudaFuncAttributeMaxDynamicSharedMemorySize, DSMEM_BYTES);
    cudaFuncSetAttribute(k_mma<1,false>, cudaFuncAttributeMaxDynamicSharedMemorySize, DSMEM_BYTES);
    cudaFuncSetAttribute(k_mma<2,false>, cudaFuncAttributeMaxDynamicSharedMemorySize, DSMEM_BYTES);
    cudaFuncSetAttribute(k_mma<3,true>,  cudaFuncAttributeMaxDynamicSharedMemorySize, DSMEM_BYTES);

    float *pX0, *pX1, *pM, *pT;
    h16 *pX0h, *pX0l, *pX1h, *pX1l, *pTh, *pSh, *pSl, *pHbh;
    h16 *pEh, *pEl, *pW0, *pWt;
    cudaGetSymbolAddress((void**)&pX0, g_X0);
    cudaGetSymbolAddress((void**)&pX1, g_X1);
    cudaGetSymbolAddress((void**)&pM,  g_M);
    cudaGetSymbolAddress((void**)&pT,  g_T);
    cudaGetSymbolAddress((void**)&pX0h, g_X0h); cudaGetSymbolAddress((void**)&pX0l, g_X0l);
    cudaGetSymbolAddress((void**)&pX1h, g_X1h); cudaGetSymbolAddress((void**)&pX1l, g_X1l);
    cudaGetSymbolAddress((void**)&pTh, g_Th);
    cudaGetSymbolAddress((void**)&pSh, g_Sh);   cudaGetSymbolAddress((void**)&pSl, g_Sl);
    cudaGetSymbolAddress((void**)&pHbh, g_Hbh);
    cudaGetSymbolAddress((void**)&pEh, g_Eh);   cudaGetSymbolAddress((void**)&pEl, g_El);
    cudaGetSymbolAddress((void**)&pW0, g_W0t);
    cudaGetSymbolAddress((void**)&pWt, g_Wt);

    // CSR build + splits (hist fused into esm split, fill fused into weight split)
    k_zero_deg<<<(N_NODES + 255) / 256, 256>>>();
    k_split_hist<<<NB_SPLIT + NB_HIST, 256>>>((const float4*)esm, (uint2*)pEh, (uint2*)pEl, dst);
    int nblk = (N_NODES + 1023) / 1024;
    k_scan_block<<<nblk, 1024>>>();
    k_scan_sums <<<1, 32>>>(nblk);
    k_finalize  <<<nblk, 1024>>>();
    k_splitW_fill<<<NB_W + NB_HIST, 256>>>(wc_W1, wc_W2, wc_W3, sc_Wn, sc_Wr, src, dst);
    k_splitT0<<<(F_IN * H + 255) / 256, 256>>>(lin0_W);

    dim3 ggrid((N_NODES + 127) / 128, 2);   // 391 x 2
    dim3 agrid((N_NODES + 3) / 4);          // 12500

    // lin0: x = esm @ W0 + b0  (T copies skipped; layer-0 agg reads X0 directly)
    k_mma<0,true><<<ggrid, 256, DSMEM_BYTES>>>(
        pEh, pEl, F_IN, pEh, pEl, 0,
        pW0, pW0,
        lin0_b, nullptr,
        pX0, pX0h, pX0l, nullptr, nullptr, nullptr,
        nullptr, nullptr, nullptr);

    float* xc = pX0;  h16* xch = pX0h; h16* xcl = pX0l;
    float* xn = pX1;  h16* xnh = pX1h; h16* xnl = pX1l;
    for (int i = 0; i < NLAYERS; i++) {
        h16* Wt1 = pWt + (size_t)(i * 5 + 0) * 65536;
        h16* Wt2 = pWt + (size_t)(i * 5 + 1) * 65536;
        h16* Wt3 = pWt + (size_t)(i * 5 + 2) * 65536;
        h16* Wtn = pWt + (size_t)(i * 5 + 3) * 65536;
        h16* Wtr = pWt + (size_t)(i * 5 + 4) * 65536;
        const float* b1 = wc_b1 + (size_t)i * H;
        const float* b2 = wc_b2 + (size_t)i * H;
        const float* b3 = wc_b3 + (size_t)i * H;
        const float* bn = sc_bn + (size_t)i * H;

        // S = A . xm   (layer 0: xm = x lives in X0; else in T)
        const float* aggIn = (i == 0) ? xc : pT;
        const h16* xmH = (i == 0) ? xch : pTh;
        k_aggregate<<<agrid, 256>>>((const float4*)aggIn, (uint2*)pSh, (uint2*)pSl);
        // h = relu(S@W2 + deg*b2 + xm@W1 + b1)   [1-term]
        k_mma<1,false><<<ggrid, 256, DSMEM_BYTES>>>(
            pSh, pSh, H, xmH, xmH, H,
            Wt2, Wt1,
            b1, b2,
            nullptr, pHbh, nullptr, nullptr, nullptr, nullptr,
            nullptr, nullptr, nullptr);
        // mask = sigmoid(h@W3 + b3) ; xg = x * mask   [1-term]
        k_mma<2,false><<<ggrid, 256, DSMEM_BYTES>>>(
            pHbh, pHbh, H, pHbh, pHbh, 0,
            Wt3, Wt3,
            b3, nullptr,
            pM, nullptr, nullptr, pT, nullptr, nullptr,
            xc, nullptr, nullptr);
        // S2 = A . xg
        k_aggregate<<<agrid, 256>>>((const float4*)pT, (uint2*)pSh, (uint2*)pSl);
        // x' = relu(S2@Wn + bn + x@Wr) ; xm_next = x'*mask ; dout block i   [2-term]
        k_mma<3,true><<<ggrid, 256, DSMEM_BYTES>>>(
            pSh, pSl, H, xch, xcl, H,
            Wtn, Wtr,
            bn, nullptr,
            xn, xnh, xnl, pT, pTh, nullptr,
            nullptr, pM, out + (size_t)i * H);

        float* tf = xc; xc = xn; xn = tf;
        h16* th = xch; xch = xnh; xnh = th;
        h16* tl = xcl; xcl = xnl; xnl = tl;
    }

    long long tail = (long long)out_size - (long long)N_NODES * (NLAYERS * H);
    if (tail > 0) {
        k_tail<<<(int)((tail + 255) / 256), 256>>>(out + (size_t)N_NODES * (NLAYERS * H), (int)tail);
    }
}

// round 7
// speedup vs baseline: 2.7819x; 1.1588x over previous
#include <cuda_runtime.h>
#include <cuda_fp16.h>
#include <math.h>
#include <stdint.h>

#define N_NODES 50000
#define N_EDGES 800000
#define H 256
#define F_IN 1280
#define NLAYERS 4

typedef __half h16;

// ---------------- scratch (device globals; no allocation) ----------------
__device__ __align__(256) float g_X0[N_NODES * H];
__device__ __align__(256) float g_X1[N_NODES * H];
__device__ __align__(256) float g_M [N_NODES * H];   // mask (fp32)
__device__ __align__(256) h16  g_X0h[N_NODES * H], g_X0l[N_NODES * H];
__device__ __align__(256) h16  g_X1h[N_NODES * H], g_X1l[N_NODES * H];
__device__ __align__(256) h16  g_Th [N_NODES * H];                    // xm / xg (fp16 hi)
__device__ __align__(256) h16  g_Sh [N_NODES * H], g_Sl [N_NODES * H];
__device__ __align__(256) h16  g_Hbh[N_NODES * H];
__device__ __align__(256) h16  g_Eh [N_NODES * F_IN];
__device__ __align__(256) h16  g_W0t[H * F_IN];                 // lin0_W transposed [n][k], fp16
__device__ __align__(256) h16  g_Wt [NLAYERS * 5 * H * H];      // per (layer,type), [n][k], fp16
__device__ int   g_deg [N_NODES];
__device__ int   g_ptr [N_NODES];
__device__ int   g_fill[N_NODES];
__device__ int   g_csr [N_EDGES];
__device__ float g_degf[N_NODES];
__device__ int   g_bsum[64];

// ---------------- helpers ----------------
__device__ __forceinline__ uint32_t smem_u32(const void* p) {
    uint32_t a;
    asm("{ .reg .u64 t; cvta.to.shared.u64 t, %1; cvt.u32.u64 %0, t; }" : "=r"(a) : "l"(p));
    return a;
}
__device__ __forceinline__ void cp16(uint32_t saddr, const void* g) {
    asm volatile("cp.async.cg.shared.global [%0], [%1], 16;" :: "r"(saddr), "l"(g));
}
__device__ __forceinline__ void cp_commit() {
    asm volatile("cp.async.commit_group;" ::: "memory");
}
template<int n>
__device__ __forceinline__ void cp_wait() {
    asm volatile("cp.async.wait_group %0;" :: "n"(n) : "memory");
}
__device__ __forceinline__ void ldm4(uint32_t a, uint32_t* r) {
    asm volatile("ldmatrix.sync.aligned.m8n8.x4.shared.b16 {%0,%1,%2,%3}, [%4];"
        : "=r"(r[0]), "=r"(r[1]), "=r"(r[2]), "=r"(r[3]) : "r"(a));
}
__device__ __forceinline__ void mma16816(float* c, const uint32_t* a, const uint32_t* b) {
    asm volatile("mma.sync.aligned.m16n8k16.row.col.f32.f16.f16.f32 "
        "{%0,%1,%2,%3}, {%4,%5,%6,%7}, {%8,%9}, {%0,%1,%2,%3};"
        : "+f"(c[0]), "+f"(c[1]), "+f"(c[2]), "+f"(c[3])
        : "r"(a[0]), "r"(a[1]), "r"(a[2]), "r"(a[3]), "r"(b[0]), "r"(b[1]));
}

__device__ __forceinline__ unsigned packh2(float a, float b) {
    __half2 t = __floats2half2_rn(a, b);
    return *(unsigned*)&t;
}
__device__ __forceinline__ uint2 packh4(float a, float b, float c, float d) {
    uint2 r; r.x = packh2(a, b); r.y = packh2(c, d); return r;
}
__device__ __forceinline__ float hlo(float a) {
    return a - __half2float(__float2half(a));
}
__device__ __forceinline__ float4 unpackh4(uint2 v) {
    float2 a = __half22float2(*(__half2*)&v.x);
    float2 b = __half22float2(*(__half2*)&v.y);
    return make_float4(a.x, a.y, b.x, b.y);
}

// ---------------- CSR build ----------------
__global__ void k_zero_deg() {
    int i = blockIdx.x * blockDim.x + threadIdx.x;
    if (i < N_NODES) g_deg[i] = 0;
}
__global__ void k_scan_block() {
    __shared__ int sh[1024];
    int i = blockIdx.x * 1024 + threadIdx.x;
    int v = (i < N_NODES) ? g_deg[i] : 0;
    sh[threadIdx.x] = v;
    __syncthreads();
    for (int off = 1; off < 1024; off <<= 1) {
        int t = (threadIdx.x >= off) ? sh[threadIdx.x - off] : 0;
        __syncthreads();
        sh[threadIdx.x] += t;
        __syncthreads();
    }
    if (i < N_NODES) g_ptr[i] = sh[threadIdx.x] - v;
    if (threadIdx.x == 1023) g_bsum[blockIdx.x] = sh[1023];
}
__global__ void k_scan_sums(int nb) {
    if (threadIdx.x == 0 && blockIdx.x == 0) {
        int run = 0;
        for (int b = 0; b < nb; b++) { int t = g_bsum[b]; g_bsum[b] = run; run += t; }
    }
}
__global__ void k_finalize() {
    int i = blockIdx.x * 1024 + threadIdx.x;
    if (i < N_NODES) {
        int p = g_ptr[i] + g_bsum[blockIdx.x];
        g_ptr[i]  = p;
        g_fill[i] = p;
        g_degf[i] = (float)g_deg[i];
    }
}

// ---------------- fused: esm split (hi only) + degree histogram ----------------
#define NB_SPLIT (N_NODES * F_IN / 4 / 256)    // 62500
#define NB_HIST  (N_EDGES / 256)               // 3125
__global__ void k_split_hist(const float4* __restrict__ src, uint2* __restrict__ hi,
                             const int* __restrict__ dst) {
    int b = blockIdx.x;
    if (b < NB_SPLIT) {
        int i = b * 256 + threadIdx.x;
        float4 v = __ldg(&src[i]);
        hi[i] = packh4(v.x, v.y, v.z, v.w);
    } else {
        int e = (b - NB_SPLIT) * 256 + threadIdx.x;
        atomicAdd(&g_deg[dst[e]], 1);
    }
}

// ---------------- fused: weight split + CSR fill ----------------
#define NB_W (5 * NLAYERS * H * H / 256)       // 5120
__global__ void k_splitW_fill(const float* __restrict__ W1, const float* __restrict__ W2,
                              const float* __restrict__ W3, const float* __restrict__ Wn,
                              const float* __restrict__ Wr,
                              const int* __restrict__ src_e, const int* __restrict__ dst_e) {
    int b = blockIdx.x;
    if (b < NB_W) {
        int i = b * 256 + threadIdx.x;
        const int per_type = NLAYERS * H * H;
        int t = i / per_type;
        int r = i - t * per_type;
        int layer = r >> 16;
        int idx = r & 65535;
        int k = idx >> 8, n = idx & 255;
        const float* src = (t == 0) ? W1 : (t == 1) ? W2 : (t == 2) ? W3 : (t == 3) ? Wn : Wr;
        size_t d = (size_t)(layer * 5 + t) * 65536 + n * 256 + k;
        g_Wt[d] = __float2half(__ldg(&src[r]));
    } else {
        int e = (b - NB_W) * 256 + threadIdx.x;
        int p = atomicAdd(&g_fill[dst_e[e]], 1);
        g_csr[p] = src_e[e];
    }
}

__global__ void k_splitT0(const float* __restrict__ W) {
    int i = blockIdx.x * blockDim.x + threadIdx.x;
    if (i < F_IN * H) {
        int k = i >> 8, n = i & 255;
        g_W0t[n * F_IN + k] = __float2half(__ldg(&W[i]));
    }
}

// ---------------- CSR gather-aggregate over fp16-hi rows -> fp16 hi(/lo) ----------------
template<bool LO>
__global__ void k_aggregate(const uint2* __restrict__ Xh,
                            uint2* __restrict__ Sh, uint2* __restrict__ Sl) {
    int node = blockIdx.x * 4 + (threadIdx.x >> 6);
    int lane = threadIdx.x & 63;
    if (node >= N_NODES) return;
    int s = g_ptr[node];
    int d = g_deg[node];
    int end = s + d;
    float4 acc = make_float4(0.f, 0.f, 0.f, 0.f);
    int e = s;
    for (; e + 4 <= end; e += 4) {
        int u0 = __ldg(&g_csr[e + 0]);
        int u1 = __ldg(&g_csr[e + 1]);
        int u2 = __ldg(&g_csr[e + 2]);
        int u3 = __ldg(&g_csr[e + 3]);
        float4 v0 = unpackh4(__ldg(&Xh[(size_t)u0 * 64 + lane]));
        float4 v1 = unpackh4(__ldg(&Xh[(size_t)u1 * 64 + lane]));
        float4 v2 = unpackh4(__ldg(&Xh[(size_t)u2 * 64 + lane]));
        float4 v3 = unpackh4(__ldg(&Xh[(size_t)u3 * 64 + lane]));
        acc.x += (v0.x + v1.x) + (v2.x + v3.x);
        acc.y += (v0.y + v1.y) + (v2.y + v3.y);
        acc.z += (v0.z + v1.z) + (v2.z + v3.z);
        acc.w += (v0.w + v1.w) + (v2.w + v3.w);
    }
    for (; e < end; e++) {
        int u = __ldg(&g_csr[e]);
        float4 v = unpackh4(__ldg(&Xh[(size_t)u * 64 + lane]));
        acc.x += v.x; acc.y += v.y; acc.z += v.z; acc.w += v.w;
    }
    size_t o = (size_t)node * 64 + lane;
    Sh[o] = packh4(acc.x, acc.y, acc.z, acc.w);
    if (LO) Sl[o] = packh4(hlo(acc.x), hlo(acc.y), hlo(acc.z), hlo(acc.w));
}

// ---------------- mma.sync GEMM: D[128 x 128] per CTA, fp16 1- or 2-term ----------------
#define ROWB 80             // 40 halves * 2B
#define OFF_AH 0
#define OFF_AL 10240
#define OFF_B  20480
#define STAGE_BYTES 30720
#define DSMEM_BYTES (2 * STAGE_BYTES + 1024)

struct Tiles {
    const h16 *A0h, *A0l, *A1h, *A1l;
    const h16 *B0, *B1;
    int K0, K1;
};

template<bool TWO>
__device__ __forceinline__ void load_stage_async(uint32_t st, int tid, int m0, int n0,
                                                 int kt, const Tiles& t) {
    const h16 *Ah, *Al, *B; int K, kl;
    if (kt < t.K0) { Ah = t.A0h; Al = t.A0l; B = t.B0; K = t.K0; kl = kt; }
    else           { Ah = t.A1h; Al = t.A1l; B = t.B1; K = t.K1; kl = kt - t.K0; }
    #pragma unroll
    for (int l = 0; l < 2; l++) {
        int f = tid + l * 256;
        int r = f >> 2, q = f & 3;
        int m = m0 + r; if (m >= N_NODES) m = N_NODES - 1;
        size_t g = (size_t)m * K + kl + q * 8;
        uint32_t s = st + r * ROWB + q * 16;
        cp16(s + OFF_AH, Ah + g);
        if (TWO) cp16(s + OFF_AL, Al + g);
    }
    #pragma unroll
    for (int l = 0; l < 2; l++) {
        int f = tid + l * 256;
        int r = f >> 2, q = f & 3;
        size_t g = (size_t)(n0 + r) * K + kl + q * 8;
        cp16(st + OFF_B + r * ROWB + q * 16, B + g);
    }
}

// MODE 0 (lin0): v = acc+b -> OA (fp32 x), OAh, OAl
// MODE 1 (h)   : v = relu(acc+b1+deg*b2) -> OAh
// MODE 2 (mask): mk=sigmoid(acc+b3) -> OA=mask (fp32); OBh = mk*Xin (xg, fp16 hi)
// MODE 3 (x')  : v = relu(acc+bn) -> OA (fp32), OAh, OAl; OBh = v*Mask (fp16 hi); Dout
template<int MODE, bool TWO>
__global__ void __launch_bounds__(256, 2) k_mma(
    const h16* A0h, const h16* A0l, int K0,
    const h16* A1h, const h16* A1l, int K1,
    const h16* B0, const h16* B1,
    const float* __restrict__ bias, const float* __restrict__ bias2,
    float* __restrict__ OA, h16* __restrict__ OAh, h16* __restrict__ OAl,
    h16* __restrict__ OBh,
    const float* __restrict__ Xin, const float* __restrict__ Mask,
    float* __restrict__ Dout)
{
    extern __shared__ char dsm_raw[];
    char* sbase = (char*)(((uintptr_t)dsm_raw + 1023) & ~(uintptr_t)1023);
    const uint32_t sb32 = smem_u32(sbase);

    const int tid = threadIdx.x;
    const int wid = tid >> 5;
    const int lane = tid & 31;
    const int wm = wid & 3;
    const int wn = wid >> 2;
    const int m0 = blockIdx.x * 128;
    const int n0 = blockIdx.y * 128;

    Tiles t; t.A0h = A0h; t.A0l = A0l; t.A1h = A1h; t.A1l = A1l;
    t.B0 = B0; t.B1 = B1; t.K0 = K0; t.K1 = K1;

    float c[2][8][4];
    #pragma unroll
    for (int i = 0; i < 2; i++)
        #pragma unroll
        for (int j = 0; j < 8; j++)
            #pragma unroll
            for (int q = 0; q < 4; q++) c[i][j][q] = 0.f;

    const int nIter = (K0 + K1) >> 5;

    load_stage_async<TWO>(sb32, tid, m0, n0, 0, t);
    cp_commit();

    const uint32_t aAddrBase = (wm * 32 + (lane & 15)) * ROWB + (lane >> 4) * 16;
    const uint32_t bAddrBase = (wn * 64 + (lane & 7) + ((lane >> 4) & 1) * 8) * ROWB
                             + ((lane >> 3) & 1) * 16;

    for (int it = 0; it < nIter; ++it) {
        const uint32_t stu = sb32 + (it & 1) * STAGE_BYTES;
        if (it + 1 < nIter) {
            load_stage_async<TWO>(sb32 + ((it + 1) & 1) * STAGE_BYTES, tid, m0, n0, (it + 1) << 5, t);
            cp_commit();
            cp_wait<1>();
        } else {
            cp_wait<0>();
        }
        __syncthreads();

        #pragma unroll
        for (int ks = 0; ks < 2; ks++) {
            const uint32_t kb = ks * 32;
            uint32_t ah[2][4], bfr[4][4];
            #pragma unroll
            for (int mt = 0; mt < 2; mt++)
                ldm4(stu + OFF_AH + aAddrBase + mt * (16 * ROWB) + kb, ah[mt]);
            #pragma unroll
            for (int nt = 0; nt < 4; nt++)
                ldm4(stu + OFF_B + bAddrBase + nt * (16 * ROWB) + kb, bfr[nt]);
            #pragma unroll
            for (int mt = 0; mt < 2; mt++)
                #pragma unroll
                for (int nt = 0; nt < 4; nt++) {
                    mma16816(c[mt][nt * 2 + 0], ah[mt], &bfr[nt][0]);
                    mma16816(c[mt][nt * 2 + 1], ah[mt], &bfr[nt][2]);
                }
            if (TWO) {
                uint32_t al[2][4];
                #pragma unroll
                for (int mt = 0; mt < 2; mt++)
                    ldm4(stu + OFF_AL + aAddrBase + mt * (16 * ROWB) + kb, al[mt]);
                #pragma unroll
                for (int mt = 0; mt < 2; mt++)
                    #pragma unroll
                    for (int nt = 0; nt < 4; nt++) {
                        mma16816(c[mt][nt * 2 + 0], al[mt], &bfr[nt][0]);
                        mma16816(c[mt][nt * 2 + 1], al[mt], &bfr[nt][2]);
                    }
            }
        }
        __syncthreads();
    }

    // ---- C regs -> smem staging, two 64-col halves (smem = 128 x 68 floats) ----
    float* stg = (float*)sbase;
    #pragma unroll
    for (int hh = 0; hh < 2; hh++) {
        if (wn == hh) {
            #pragma unroll
            for (int mt = 0; mt < 2; mt++) {
                #pragma unroll
                for (int nt = 0; nt < 8; nt++) {
                    int r0 = wm * 32 + mt * 16 + (lane >> 2);
                    int col = nt * 8 + (lane & 3) * 2;
                    *(float2*)&stg[r0 * 68 + col]       = make_float2(c[mt][nt][0], c[mt][nt][1]);
                    *(float2*)&stg[(r0 + 8) * 68 + col] = make_float2(c[mt][nt][2], c[mt][nt][3]);
                }
            }
        }
        __syncthreads();

        #pragma unroll
        for (int p = 0; p < 8; p++) {
            int f = tid + p * 256;
            int row = f >> 4;
            int c4 = f & 15;
            int m = m0 + row;
            if (m < N_NODES) {
                int col = c4 * 4;
                int gcol = n0 + hh * 64 + col;
                float4 v = *(float4*)&stg[row * 68 + col];
                float4 b4 = __ldg((const float4*)(bias + gcol));
                float v0 = v.x + b4.x, v1 = v.y + b4.y, v2 = v.z + b4.z, v3 = v.w + b4.w;
                size_t off = (size_t)m * H + gcol;
                if (MODE == 0) {
                    *(float4*)(OA + off) = make_float4(v0, v1, v2, v3);
                    *(uint2*)(OAh + off) = packh4(v0, v1, v2, v3);
                    *(uint2*)(OAl + off) = packh4(hlo(v0), hlo(v1), hlo(v2), hlo(v3));
                }
                if (MODE == 1) {
                    float dv = g_degf[m];
                    float4 b2v = __ldg((const float4*)(bias2 + gcol));
                    v0 = fmaxf(v0 + dv * b2v.x, 0.f);
                    v1 = fmaxf(v1 + dv * b2v.y, 0.f);
                    v2 = fmaxf(v2 + dv * b2v.z, 0.f);
                    v3 = fmaxf(v3 + dv * b2v.w, 0.f);
                    *(uint2*)(OAh + off) = packh4(v0, v1, v2, v3);
                }
                if (MODE == 2) {
                    v0 = 1.f / (1.f + expf(-v0));
                    v1 = 1.f / (1.f + expf(-v1));
                    v2 = 1.f / (1.f + expf(-v2));
                    v3 = 1.f / (1.f + expf(-v3));
                    *(float4*)(OA + off) = make_float4(v0, v1, v2, v3);
                    float4 xv = __ldg((const float4*)(Xin + off));
                    *(uint2*)(OBh + off) = packh4(v0 * xv.x, v1 * xv.y, v2 * xv.z, v3 * xv.w);
                }
                if (MODE == 3) {
                    v0 = fmaxf(v0, 0.f); v1 = fmaxf(v1, 0.f);
                    v2 = fmaxf(v2, 0.f); v3 = fmaxf(v3, 0.f);
                    *(float4*)(OA + off) = make_float4(v0, v1, v2, v3);
                    *(uint2*)(OAh + off) = packh4(v0, v1, v2, v3);
                    *(uint2*)(OAl + off) = packh4(hlo(v0), hlo(v1), hlo(v2), hlo(v3));
                    float4 mv = __ldg((const float4*)(Mask + off));
                    *(uint2*)(OBh + off) = packh4(v0 * mv.x, v1 * mv.y, v2 * mv.z, v3 * mv.w);
                    *(float4*)(Dout + (size_t)m * (NLAYERS * H) + gcol) = make_float4(v0, v1, v2, v3);
                }
            }
        }
        __syncthreads();
    }
}

__global__ void k_tail(float* p, int n) {
    int i = blockIdx.x * blockDim.x + threadIdx.x;
    if (i < n) p[i] = 1.0f;
}

// ---------------- launch ----------------
extern "C" void kernel_launch(void* const* d_in, const int* in_sizes, int n_in,
                              void* d_out, int out_size)
{
    (void)in_sizes; (void)n_in;
    const int*   edge   = (const int*)  d_in[1];
    const float* esm    = (const float*)d_in[2];
    const float* lin0_W = (const float*)d_in[4];
    const float* lin0_b = (const float*)d_in[5];
    const float* wc_W1  = (const float*)d_in[6];
    const float* wc_b1  = (const float*)d_in[7];
    const float* wc_W2  = (const float*)d_in[8];
    const float* wc_b2  = (const float*)d_in[9];
    const float* wc_W3  = (const float*)d_in[10];
    const float* wc_b3  = (const float*)d_in[11];
    const float* sc_Wn  = (const float*)d_in[12];
    const float* sc_bn  = (const float*)d_in[13];
    const float* sc_Wr  = (const float*)d_in[14];
    float* out = (float*)d_out;

    const int* src = edge;
    const int* dst = edge + N_EDGES;

    cudaFuncSetAttribute(k_mma<0,false>, cudaFuncAttributeMaxDynamicSharedMemorySize, DSMEM_BYTES);
    cudaFuncSetAttribute(k_mma<1,false>, cudaFuncAttributeMaxDynamicSharedMemorySize, DSMEM_BYTES);
    cudaFuncSetAttribute(k_mma<2,false>, cudaFuncAttributeMaxDynamicSharedMemorySize, DSMEM_BYTES);
    cudaFuncSetAttribute(k_mma<3,true>,  cudaFuncAttributeMaxDynamicSharedMemorySize, DSMEM_BYTES);

    float *pX0, *pX1, *pM;
    h16 *pX0h, *pX0l, *pX1h, *pX1l, *pTh, *pSh, *pSl, *pHbh;
    h16 *pEh, *pW0, *pWt;
    cudaGetSymbolAddress((void**)&pX0, g_X0);
    cudaGetSymbolAddress((void**)&pX1, g_X1);
    cudaGetSymbolAddress((void**)&pM,  g_M);
    cudaGetSymbolAddress((void**)&pX0h, g_X0h); cudaGetSymbolAddress((void**)&pX0l, g_X0l);
    cudaGetSymbolAddress((void**)&pX1h, g_X1h); cudaGetSymbolAddress((void**)&pX1l, g_X1l);
    cudaGetSymbolAddress((void**)&pTh, g_Th);
    cudaGetSymbolAddress((void**)&pSh, g_Sh);   cudaGetSymbolAddress((void**)&pSl, g_Sl);
    cudaGetSymbolAddress((void**)&pHbh, g_Hbh);
    cudaGetSymbolAddress((void**)&pEh, g_Eh);
    cudaGetSymbolAddress((void**)&pW0, g_W0t);
    cudaGetSymbolAddress((void**)&pWt, g_Wt);

    // CSR build + splits (hist fused into esm split, fill fused into weight split)
    k_zero_deg<<<(N_NODES + 255) / 256, 256>>>();
    k_split_hist<<<NB_SPLIT + NB_HIST, 256>>>((const float4*)esm, (uint2*)pEh, dst);
    int nblk = (N_NODES + 1023) / 1024;
    k_scan_block<<<nblk, 1024>>>();
    k_scan_sums <<<1, 32>>>(nblk);
    k_finalize  <<<nblk, 1024>>>();
    k_splitW_fill<<<NB_W + NB_HIST, 256>>>(wc_W1, wc_W2, wc_W3, sc_Wn, sc_Wr, src, dst);
    k_splitT0<<<(F_IN * H + 255) / 256, 256>>>(lin0_W);

    dim3 ggrid((N_NODES + 127) / 128, 2);   // 391 x 2
    dim3 agrid((N_NODES + 3) / 4);          // 12500

    // lin0: x = esm @ W0 + b0  (1-term, hi-only esm)
    k_mma<0,false><<<ggrid, 256, DSMEM_BYTES>>>(
        pEh, pEh, F_IN, pEh, pEh, 0,
        pW0, pW0,
        lin0_b, nullptr,
        pX0, pX0h, pX0l, nullptr,
        nullptr, nullptr, nullptr);

    float* xc = pX0;  h16* xch = pX0h; h16* xcl = pX0l;
    float* xn = pX1;  h16* xnh = pX1h; h16* xnl = pX1l;
    for (int i = 0; i < NLAYERS; i++) {
        h16* Wt1 = pWt + (size_t)(i * 5 + 0) * 65536;
        h16* Wt2 = pWt + (size_t)(i * 5 + 1) * 65536;
        h16* Wt3 = pWt + (size_t)(i * 5 + 2) * 65536;
        h16* Wtn = pWt + (size_t)(i * 5 + 3) * 65536;
        h16* Wtr = pWt + (size_t)(i * 5 + 4) * 65536;
        const float* b1 = wc_b1 + (size_t)i * H;
        const float* b2 = wc_b2 + (size_t)i * H;
        const float* b3 = wc_b3 + (size_t)i * H;
        const float* bn = sc_bn + (size_t)i * H;

        // S = A . xm   (fp16-hi gather; layer 0: xm = x -> X0h, else Th)
        const h16* xmH = (i == 0) ? xch : pTh;
        k_aggregate<false><<<agrid, 256>>>((const uint2*)xmH, (uint2*)pSh, nullptr);
        // h = relu(S@W2 + deg*b2 + xm@W1 + b1)   [1-term]
        k_mma<1,false><<<ggrid, 256, DSMEM_BYTES>>>(
            pSh, pSh, H, xmH, xmH, H,
            Wt2, Wt1,
            b1, b2,
            nullptr, pHbh, nullptr, nullptr,
            nullptr, nullptr, nullptr);
        // mask = sigmoid(h@W3 + b3) ; xg = x * mask (fp16 hi)   [1-term]
        k_mma<2,false><<<ggrid, 256, DSMEM_BYTES>>>(
            pHbh, pHbh, H, pHbh, pHbh, 0,
            Wt3, Wt3,
            b3, nullptr,
            pM, nullptr, nullptr, pTh,
            xc, nullptr, nullptr);
        // S2 = A . xg   (fp16-hi gather, hi+lo output for 2-term GEMM)
        k_aggregate<true><<<agrid, 256>>>((const uint2*)pTh, (uint2*)pSh, (uint2*)pSl);
        // x' = relu(S2@Wn + bn + x@Wr) ; xm_next = x'*mask (fp16 hi) ; dout block i   [2-term]
        k_mma<3,true><<<ggrid, 256, DSMEM_BYTES>>>(
            pSh, pSl, H, xch, xcl, H,
            Wtn, Wtr,
            bn, nullptr,
            xn, xnh, xnl, pTh,
            nullptr, pM, out + (size_t)i * H);

        float* tf = xc; xc = xn; xn = tf;
        h16* th = xch; xch = xnh; xnh = th;
        h16* tl = xcl; xcl = xnl; xnl = tl;
    }

    long long tail = (long long)out_size - (long long)N_NODES * (NLAYERS * H);
    if (tail > 0) {
        k_tail<<<(int)((tail + 255) / 256), 256>>>(out + (size_t)N_NODES * (NLAYERS * H), (int)tail);
    }
}